// round 13
// baseline (speedup 1.0000x reference)
#include <cuda_runtime.h>
#include <cuda_bf16.h>
#include <cuda_fp16.h>
#include <math.h>
#include <stdint.h>

// ---------------- problem constants ----------------
#define Bc   2
#define Tc   2048
#define Dc   1024
#define Hc   16
#define HDc  64
#define DFFc 4096
#define Lc   8
#define Vc   50257
#define BTc  (Bc*Tc)          // 4096
#define EPSc 1e-5f

// ---------------- static device scratch (no allocs allowed) ----------------
__device__ float  g_h  [BTc*Dc];
__device__ float  g_fin[Bc*Dc];
__device__ __half g_xnh [BTc*Dc];
__device__ __half g_qh  [BTc*Dc];
__device__ __half g_kh  [BTc*Dc];
__device__ __half g_vh  [BTc*Dc];
__device__ __half g_ctxh[BTc*Dc];
__device__ __half g_ffh [(long)BTc*DFFc];
// fp16 weights (converted once per launch)
__device__ __half g_wq16[(long)Lc*Dc*Dc];
__device__ __half g_wk16[(long)Lc*Dc*Dc];
__device__ __half g_wv16[(long)Lc*Dc*Dc];
__device__ __half g_wo16[(long)Lc*Dc*Dc];
__device__ __half g_w116[(long)Lc*DFFc*Dc];
__device__ __half g_w216[(long)Lc*DFFc*Dc];

// ---------------- helpers ----------------
__device__ __forceinline__ float gelu_f(float x) {
    const float c = 0.7978845608028654f;
    return 0.5f * x * (1.0f + tanhf(c * (x + 0.044715f * x * x * x)));
}
__device__ __forceinline__ void mma_f16(float* c, const uint32_t* a, const uint32_t* b) {
    asm volatile(
        "mma.sync.aligned.m16n8k16.row.col.f32.f16.f16.f32 "
        "{%0,%1,%2,%3}, {%4,%5,%6,%7}, {%8,%9}, {%0,%1,%2,%3};"
        : "+f"(c[0]), "+f"(c[1]), "+f"(c[2]), "+f"(c[3])
        : "r"(a[0]), "r"(a[1]), "r"(a[2]), "r"(a[3]), "r"(b[0]), "r"(b[1]));
}
__device__ __forceinline__ uint32_t h2pack(float a, float b) {
    __half2 h = __floats2half2_rn(a, b);
    return *(uint32_t*)&h;
}

// ---------------- fp32 -> fp16 conversion (weights, once per launch) --------
__global__ void cvtk(const float* __restrict__ s, __half* __restrict__ d, long n)
{
    long i = ((long)blockIdx.x * blockDim.x + threadIdx.x) * 4;
    if (i >= n) return;
    float4 v = *(const float4*)(s + i);
    uint2 o;
    o.x = h2pack(v.x, v.y);
    o.y = h2pack(v.z, v.w);
    *(uint2*)(d + i) = o;
}

// ---------------- embedding ----------------
__global__ void embed_k(const int* __restrict__ x,
                        const float* __restrict__ Wemb,
                        const float* __restrict__ pos,
                        float* __restrict__ h)
{
    long i = (long)blockIdx.x * blockDim.x + threadIdx.x;
    if (i >= (long)BTc * Dc) return;
    int row = (int)(i / Dc);
    int d   = (int)(i % Dc);
    int t   = row % Tc;
    int tok = x[row];
    h[i] = Wemb[(long)tok * Dc + d] + pos[(long)t * Dc + d];
}

// ---------------- layernorm (ddof=1, std+eps), fp16 or fp32 output ---------
__global__ void ln_k(const float* __restrict__ in, long inStride,
                     void* __restrict__ out, long outStride, int outHalf,
                     const float* __restrict__ sc, const float* __restrict__ sh)
{
    __shared__ float red[256];
    int r = blockIdx.x, tid = threadIdx.x;
    const float* x = in + (long)r * inStride;
    float xv[4];
    float s = 0.f;
#pragma unroll
    for (int i = 0; i < 4; i++) { xv[i] = x[tid + i * 256]; s += xv[i]; }
    red[tid] = s; __syncthreads();
    for (int st = 128; st > 0; st >>= 1) { if (tid < st) red[tid] += red[tid + st]; __syncthreads(); }
    float mean = red[0] * (1.0f / (float)Dc);
    __syncthreads();
    float v = 0.f;
#pragma unroll
    for (int i = 0; i < 4; i++) { float t = xv[i] - mean; v += t * t; }
    red[tid] = v; __syncthreads();
    for (int st = 128; st > 0; st >>= 1) { if (tid < st) red[tid] += red[tid + st]; __syncthreads(); }
    float inv = 1.0f / (sqrtf(red[0] / (float)(Dc - 1)) + EPSc);
#pragma unroll
    for (int i = 0; i < 4; i++) {
        int d = tid + i * 256;
        float o = sc[d] * ((xv[i] - mean) * inv) + sh[d];
        if (outHalf) ((__half*)out)[(long)r * outStride + d] = __float2half_rn(o);
        else         ((float*)out)[(long)r * outStride + d] = o;
    }
}

// =====================================================================
// flash_k (R12-proven, fp16 I/O): fused causal attention, q-tile 128 rows.
// =====================================================================
__global__ __launch_bounds__(256)
void flash_k(const __half* __restrict__ Qg, const __half* __restrict__ Kg,
             const __half* __restrict__ Vg, __half* __restrict__ Og)
{
    __shared__ uint32_t usm[4608];           // 18432 B
    uint32_t* Qsh = usm;                     // [128][36]
    uint32_t* sKf = usm;                     // [4][8][64] = 8KB
    uint32_t* sVf = usm + 2048;              // [4][8][64] = 8KB

    int qt = (int)gridDim.x - 1 - blockIdx.x;
    int q0 = qt * 128;
    int z  = blockIdx.y;
    int b  = z / Hc, hh = z % Hc;
    long base = (long)b * Tc * Dc + (long)hh * HDc;
    const __half* Qb = Qg + base;
    const __half* Kb = Kg + base;
    const __half* Vb = Vg + base;
    __half* Ob = Og + base;

    int tid = threadIdx.x, lane = tid & 31, warp = tid >> 5;
    int g = lane >> 2, c = lane & 3;
    int physC = lane ^ ((lane >> 3) & 3);

    {
        int kr = tid >> 1, half = tid & 1;
        const uint4* src = (const uint4*)(Qb + (long)(q0 + kr) * Dc + half * 32);
        uint32_t* dst = Qsh + kr * 36 + half * 16;
#pragma unroll
        for (int f = 0; f < 4; f++)
            *(uint4*)(dst + f * 4) = src[f];
    }
    __syncthreads();

    uint32_t qf[4][4];
    {
        int r0w = warp * 16 + g;
#pragma unroll
        for (int kb = 0; kb < 4; kb++) {
            int w = kb * 8 + c;
            qf[kb][0] = Qsh[r0w * 36 + w];
            qf[kb][1] = Qsh[(r0w + 8) * 36 + w];
            qf[kb][2] = Qsh[r0w * 36 + w + 4];
            qf[kb][3] = Qsh[(r0w + 8) * 36 + w + 4];
        }
    }
    __syncthreads();

    float oacc[8][4];
#pragma unroll
    for (int i = 0; i < 8; i++)
#pragma unroll
        for (int e = 0; e < 4; e++) oacc[i][e] = 0.f;
    float m0 = -1e30f, m1 = -1e30f, l0 = 0.f, l1 = 0.f;

    bool isK = tid < 128;
    int t = isK ? tid : (tid - 128);
    int nK  = t & 63;
    int kqK = t >> 6;
    int nbK = nK >> 3, gK = nK & 7;
    int swzK = (gK >> 1) & 3;
    int nbxK = (nbK & 1) << 3;
    const __half* KpBase = Kb + (long)nK * Dc + kqK * 32;
    int kV = t & 63;
    int chV = t >> 6;
    int kbV = kV >> 4, kkV = kV & 15;
    int cV  = (kkV & 7) >> 1, hfV = (kkV >> 3) & 1, loV = kkV & 1;
    const __half* VpBase = Vb + (long)kV * Dc + chV * 32;

    int nkt = 2 * qt + 2;
    for (int kt = 0; kt < nkt; kt++) {
        int k0 = kt * 64;

        if (isK) {
#pragma unroll
            for (int i = 0; i < 2; i++) {
                int kb = 2 * kqK + i;
                const uint4* ps = (const uint4*)(KpBase + (long)k0 * Dc + i * 16);
                uint4 u0 = ps[0], u1 = ps[1];
                const uint32_t* W0 = (const uint32_t*)&u0;
                const uint32_t* W1 = (const uint32_t*)&u1;
                uint32_t* dst = sKf + kb * 512 + nbK * 64;
#pragma unroll
                for (int cc = 0; cc < 4; cc++) {
                    int s = ((4 * gK + cc) ^ swzK) ^ nbxK;
                    dst[s * 2 + 0] = W0[cc];
                    dst[s * 2 + 1] = W1[cc];
                }
            }
        } else {
            const uint4* vp = (const uint4*)(VpBase + (long)k0 * Dc);
            uint32_t* dstK = sVf + kbV * 512;
#pragma unroll
            for (int u = 0; u < 4; u++) {
                uint4 vv = vp[u];
                const uint32_t* W = (const uint32_t*)&vv;
#pragma unroll
                for (int w = 0; w < 4; w++) {
                    __half2 h2 = *(__half2*)&W[w];
#pragma unroll
                    for (int hw = 0; hw < 2; hw++) {
                        int j = u * 8 + w * 2 + hw;
                        int n = chV * 32 + j;
                        int nb = n >> 3, gg = n & 7;
                        int s = ((4 * gg + cV) ^ ((gg >> 1) & 3)) ^ ((nb & 1) << 3);
                        __half* hp = (__half*)&dstK[nb * 64 + s * 2 + hfV];
                        hp[loV] = hw ? __high2half(h2) : __low2half(h2);
                    }
                }
            }
        }
        __syncthreads();

        bool active = (k0 <= q0 + warp * 16 + 15);
        if (active) {
            float sacc[8][4];
#pragma unroll
            for (int i = 0; i < 8; i++)
#pragma unroll
                for (int e = 0; e < 4; e++) sacc[i][e] = 0.f;
#pragma unroll
            for (int kb = 0; kb < 4; kb++) {
#pragma unroll
                for (int nb = 0; nb < 8; nb++) {
                    uint2 bk = *(uint2*)&sKf[kb * 512 + nb * 64 +
                                             (physC ^ ((nb & 1) << 3)) * 2];
                    mma_f16(sacc[nb], qf[kb], &bk.x);
                }
            }

            int qr0 = q0 + warp * 16 + g;
            int qr1 = qr0 + 8;
            bool maskNeed = (k0 + 63 > q0 + warp * 16);
            float rm0 = -1e30f, rm1 = -1e30f;
#pragma unroll
            for (int ni = 0; ni < 8; ni++) {
#pragma unroll
                for (int e = 0; e < 4; e++) {
                    float vvv = sacc[ni][e] * 0.125f;
                    if (maskNeed) {
                        int kc = k0 + ni * 8 + c * 2 + (e & 1);
                        if (kc > ((e >= 2) ? qr1 : qr0)) vvv = -1e30f;
                    }
                    sacc[ni][e] = vvv;
                    if (e < 2) rm0 = fmaxf(rm0, vvv); else rm1 = fmaxf(rm1, vvv);
                }
            }
            rm0 = fmaxf(rm0, __shfl_xor_sync(0xffffffffu, rm0, 1));
            rm0 = fmaxf(rm0, __shfl_xor_sync(0xffffffffu, rm0, 2));
            rm1 = fmaxf(rm1, __shfl_xor_sync(0xffffffffu, rm1, 1));
            rm1 = fmaxf(rm1, __shfl_xor_sync(0xffffffffu, rm1, 2));
            float mn0 = fmaxf(m0, rm0), mn1 = fmaxf(m1, rm1);
            float sc0 = __expf(m0 - mn0), sc1 = __expf(m1 - mn1);
            float rs0 = 0.f, rs1 = 0.f;
#pragma unroll
            for (int ni = 0; ni < 8; ni++) {
#pragma unroll
                for (int e = 0; e < 4; e++) {
                    float ee = __expf(sacc[ni][e] - ((e < 2) ? mn0 : mn1));
                    sacc[ni][e] = ee;
                    if (e < 2) rs0 += ee; else rs1 += ee;
                }
            }
            rs0 += __shfl_xor_sync(0xffffffffu, rs0, 1);
            rs0 += __shfl_xor_sync(0xffffffffu, rs0, 2);
            rs1 += __shfl_xor_sync(0xffffffffu, rs1, 1);
            rs1 += __shfl_xor_sync(0xffffffffu, rs1, 2);
            l0 = l0 * sc0 + rs0;
            l1 = l1 * sc1 + rs1;
            m0 = mn0; m1 = mn1;
#pragma unroll
            for (int ni = 0; ni < 8; ni++) {
#pragma unroll
                for (int e = 0; e < 4; e++) oacc[ni][e] *= (e < 2) ? sc0 : sc1;
            }

#pragma unroll
            for (int kb = 0; kb < 4; kb++) {
                uint32_t pf[4];
                pf[0] = h2pack(sacc[2 * kb][0],     sacc[2 * kb][1]);
                pf[1] = h2pack(sacc[2 * kb][2],     sacc[2 * kb][3]);
                pf[2] = h2pack(sacc[2 * kb + 1][0], sacc[2 * kb + 1][1]);
                pf[3] = h2pack(sacc[2 * kb + 1][2], sacc[2 * kb + 1][3]);
#pragma unroll
                for (int nb = 0; nb < 8; nb++) {
                    uint2 bv = *(uint2*)&sVf[kb * 512 + nb * 64 +
                                             (physC ^ ((nb & 1) << 3)) * 2];
                    mma_f16(oacc[nb], pf, &bv.x);
                }
            }
        }
        __syncthreads();
    }

    float il0 = 1.f / l0, il1 = 1.f / l1;
    int r0 = q0 + warp * 16 + g;
#pragma unroll
    for (int ni = 0; ni < 8; ni++) {
        int d = ni * 8 + 2 * c;
        *(uint32_t*)(Ob + (long)r0 * Dc + d) =
            h2pack(oacc[ni][0] * il0, oacc[ni][1] * il0);
        *(uint32_t*)(Ob + (long)(r0 + 8) * Dc + d) =
            h2pack(oacc[ni][2] * il1, oacc[ni][3] * il1);
    }
}

// =====================================================================
// gemm_h2: dense NT GEMM, fp16 operands, fp32 accum.
// 128(M) x 256(N) block, 8 warps of 64x64 tiles, 256 threads, 1 CTA/SM.
// BK=16, double-buffered register-prefetch pipeline.
// C = A[M,K] @ B[N,K]^T [+bias][gelu][+resid]; out fp16 or fp32.
// Requires M%128==0, N%256==0, K%16==0.
// =====================================================================
__global__ __launch_bounds__(256, 1)
void gemm_h2(const __half* __restrict__ A, int lda,
             const __half* __restrict__ B, int ldb,
             void* __restrict__ Cp, int ldc, int K,
             const float* __restrict__ bias,
             const float* __restrict__ resid, int doGelu, int outHalf)
{
    __shared__ uint32_t sAx[2][8][128];     // 4KB/stage
    __shared__ uint32_t sBx[2][32][64];     // 8KB/stage

    int m0 = blockIdx.y * 128, n0 = blockIdx.x * 256;
    int tid = threadIdx.x, lane = tid & 31, warp = tid >> 5;
    int wm = (warp & 1) * 64, wn = (warp >> 1) * 64;
    int bA0 = wm >> 4, nb0 = wn >> 3;

    float acc[4][8][4];
#pragma unroll
    for (int i = 0; i < 4; i++)
#pragma unroll
        for (int jx = 0; jx < 8; jx++)
#pragma unroll
            for (int e = 0; e < 4; e++) acc[i][jx][e] = 0.f;

    // A staging role (2 threads per row)
    int rA = tid >> 1, hfA = tid & 1;
    int jA = rA >> 4, gA = rA & 7, hiA = (rA >> 3) & 1;
    int swzA = (gA >> 1) & 3;
    const __half* Ap = A + (long)(m0 + rA) * lda + hfA * 8;
    // B staging role (1 thread per row, full 16 halves)
    int rB = tid;
    int nbB = rB >> 3, gB = rB & 7;
    int swzB = (gB >> 1) & 3;
    int nbxB = (nbB & 1) << 3;
    const __half* Bp = B + (long)(n0 + rB) * ldb;

    int nIter = K / 16;

    uint4 pa  = *(const uint4*)Ap;
    uint4 pb0 = *(const uint4*)Bp;
    uint4 pb1 = *(const uint4*)(Bp + 8);

    {
        const uint32_t* WA  = (const uint32_t*)&pa;
        const uint32_t* WB0 = (const uint32_t*)&pb0;
        const uint32_t* WB1 = (const uint32_t*)&pb1;
        uint32_t* aw = sAx[0][jA];
        uint32_t* bw = sBx[0][nbB];
#pragma unroll
        for (int c = 0; c < 4; c++) {
            int phA = (4 * gA + c) ^ swzA;
            aw[phA * 4 + hiA + 2 * hfA] = WA[c];
            int s = ((4 * gB + c) ^ swzB) ^ nbxB;
            bw[s * 2 + 0] = WB0[c];
            bw[s * 2 + 1] = WB1[c];
        }
    }
    __syncthreads();

    int physC = lane ^ ((lane >> 3) & 3);

    for (int it = 0; it < nIter; it++) {
        int cur = it & 1;
        bool more = (it + 1) < nIter;
        if (more) {
            long ko = (long)(it + 1) * 16;
            pa  = *(const uint4*)(Ap + ko);
            pb0 = *(const uint4*)(Bp + ko);
            pb1 = *(const uint4*)(Bp + ko + 8);
        }

        // ---- mma: 4 m-blocks x 8 n-blocks ----
        {
            float4 af[4]; float2 bf[8];
#pragma unroll
            for (int mi = 0; mi < 4; mi++)
                af[mi] = ((const float4*)sAx[cur][bA0 + mi])[physC];
#pragma unroll
            for (int ni = 0; ni < 8; ni++) {
                int nb2 = nb0 + ni;
                bf[ni] = ((const float2*)sBx[cur][nb2])[physC ^ ((nb2 & 1) << 3)];
            }
#pragma unroll
            for (int mi = 0; mi < 4; mi++)
#pragma unroll
                for (int ni = 0; ni < 8; ni++)
                    mma_f16(acc[mi][ni], (const uint32_t*)&af[mi], (const uint32_t*)&bf[ni]);
        }

        if (more) {
            int nxt = cur ^ 1;
            const uint32_t* WA  = (const uint32_t*)&pa;
            const uint32_t* WB0 = (const uint32_t*)&pb0;
            const uint32_t* WB1 = (const uint32_t*)&pb1;
            uint32_t* aw = sAx[nxt][jA];
            uint32_t* bw = sBx[nxt][nbB];
#pragma unroll
            for (int c = 0; c < 4; c++) {
                int phA = (4 * gA + c) ^ swzA;
                aw[phA * 4 + hiA + 2 * hfA] = WA[c];
                int s = ((4 * gB + c) ^ swzB) ^ nbxB;
                bw[s * 2 + 0] = WB0[c];
                bw[s * 2 + 1] = WB1[c];
            }
        }
        __syncthreads();
    }

    // ---- epilogue ----
    int ge = lane >> 2, c2 = (lane & 3) * 2;
#pragma unroll
    for (int mi = 0; mi < 4; mi++) {
#pragma unroll
        for (int ni = 0; ni < 8; ni++) {
            int gm = m0 + wm + mi * 16 + ge;
            int gn = n0 + wn + ni * 8 + c2;
            float v0 = acc[mi][ni][0], v1 = acc[mi][ni][1];
            float v2 = acc[mi][ni][2], v3 = acc[mi][ni][3];
            if (bias) {
                float b0 = bias[gn], b1 = bias[gn + 1];
                v0 += b0; v1 += b1; v2 += b0; v3 += b1;
            }
            if (doGelu) { v0 = gelu_f(v0); v1 = gelu_f(v1); v2 = gelu_f(v2); v3 = gelu_f(v3); }
            if (resid) {
                const float* r0p = resid + (long)gm * ldc + gn;
                const float* r1p = resid + (long)(gm + 8) * ldc + gn;
                v0 += r0p[0]; v1 += r0p[1]; v2 += r1p[0]; v3 += r1p[1];
            }
            if (outHalf) {
                __half* C = (__half*)Cp;
                *(uint32_t*)(C + (long)gm * ldc + gn)       = h2pack(v0, v1);
                *(uint32_t*)(C + (long)(gm + 8) * ldc + gn) = h2pack(v2, v3);
            } else {
                float* C = (float*)Cp;
                *(float2*)(C + (long)gm * ldc + gn)       = make_float2(v0, v1);
                *(float2*)(C + (long)(gm + 8) * ldc + gn) = make_float2(v2, v3);
            }
        }
    }
}

// ---------------- dedicated logits kernel (M=2, fp32, memory-bound) ----------
__global__ __launch_bounds__(256)
void logits_k(const float* __restrict__ fin,
              const float* __restrict__ Wemb,
              float* __restrict__ out)
{
    __shared__ float f0[Dc], f1[Dc];
    int tid = threadIdx.x;
    for (int i = tid; i < Dc; i += 256) { f0[i] = fin[i]; f1[i] = fin[Dc + i]; }
    __syncthreads();
    int warp = tid >> 5, lane = tid & 31;
    long v = (long)blockIdx.x * 8 + warp;
    if (v >= Vc) return;
    const float* w = Wemb + v * Dc;
    float d0 = 0.f, d1 = 0.f;
    for (int i = lane * 4; i < Dc; i += 128) {
        float4 wv = *(const float4*)(w + i);
        d0 += wv.x * f0[i] + wv.y * f0[i+1] + wv.z * f0[i+2] + wv.w * f0[i+3];
        d1 += wv.x * f1[i] + wv.y * f1[i+1] + wv.z * f1[i+2] + wv.w * f1[i+3];
    }
#pragma unroll
    for (int o = 16; o > 0; o >>= 1) {
        d0 += __shfl_xor_sync(0xffffffff, d0, o);
        d1 += __shfl_xor_sync(0xffffffff, d1, o);
    }
    if (lane == 0) { out[v] = d0; out[(long)Vc + v] = d1; }
}

// ---------------- host-side launch helpers ----------------
static inline void launch_h(const __half* A, int lda, const __half* B, int ldb,
                            void* C, int ldc, int M, int N, int K,
                            const float* bias, const float* resid,
                            int gelu, int outHalf)
{
    dim3 g(N / 256, M / 128, 1);
    gemm_h2<<<g, 256>>>(A, lda, B, ldb, C, ldc, K, bias, resid, gelu, outHalf);
}
static inline void launch_cvt(const float* s, __half* d, long n)
{
    long blocks = (n / 4 + 255) / 256;
    cvtk<<<(unsigned)blocks, 256>>>(s, d, n);
}

extern "C" void kernel_launch(void* const* d_in, const int* in_sizes, int n_in,
                              void* d_out, int out_size)
{
    const int*   x    = (const int*)  d_in[0];
    const float* Wemb = (const float*)d_in[1];
    const float* pos  = (const float*)d_in[2];
    const float* Wq   = (const float*)d_in[3];
    const float* Wk   = (const float*)d_in[4];
    const float* Wv   = (const float*)d_in[5];
    const float* Wo   = (const float*)d_in[6];
    const float* bo   = (const float*)d_in[7];
    const float* n1s  = (const float*)d_in[8];
    const float* n1b  = (const float*)d_in[9];
    const float* n2s  = (const float*)d_in[10];
    const float* n2b  = (const float*)d_in[11];
    const float* W1   = (const float*)d_in[12];
    const float* b1   = (const float*)d_in[13];
    const float* W2   = (const float*)d_in[14];
    const float* b2   = (const float*)d_in[15];
    const float* fs   = (const float*)d_in[16];
    const float* fb   = (const float*)d_in[17];
    float* out = (float*)d_out;

    float  *h, *fin;
    __half *xnh, *qh, *kh, *vh, *ctxh, *ffh;
    __half *wq16, *wk16, *wv16, *wo16, *w116, *w216;
    cudaGetSymbolAddress((void**)&h,    g_h);
    cudaGetSymbolAddress((void**)&fin,  g_fin);
    cudaGetSymbolAddress((void**)&xnh,  g_xnh);
    cudaGetSymbolAddress((void**)&qh,   g_qh);
    cudaGetSymbolAddress((void**)&kh,   g_kh);
    cudaGetSymbolAddress((void**)&vh,   g_vh);
    cudaGetSymbolAddress((void**)&ctxh, g_ctxh);
    cudaGetSymbolAddress((void**)&ffh,  g_ffh);
    cudaGetSymbolAddress((void**)&wq16, g_wq16);
    cudaGetSymbolAddress((void**)&wk16, g_wk16);
    cudaGetSymbolAddress((void**)&wv16, g_wv16);
    cudaGetSymbolAddress((void**)&wo16, g_wo16);
    cudaGetSymbolAddress((void**)&w116, g_w116);
    cudaGetSymbolAddress((void**)&w216, g_w216);

    const long TD = (long)Tc * Dc;
    const long DD = (long)Dc * Dc;
    const long FD = (long)DFFc * Dc;

    // weights -> fp16 (once per launch; graph-capturable)
    launch_cvt(Wq, wq16, (long)Lc * DD);
    launch_cvt(Wk, wk16, (long)Lc * DD);
    launch_cvt(Wv, wv16, (long)Lc * DD);
    launch_cvt(Wo, wo16, (long)Lc * DD);
    launch_cvt(W1, w116, (long)Lc * FD);
    launch_cvt(W2, w216, (long)Lc * FD);

    {
        long n = (long)BTc * Dc;
        embed_k<<<(unsigned)((n + 255) / 256), 256>>>(x, Wemb, pos, h);
    }

    for (int l = 0; l < Lc; l++) {
        const float* bol = bo + (long)l * Dc;
        const float* b1l = b1 + (long)l * DFFc;
        const float* b2l = b2 + (long)l * Dc;

        // LN1 -> fp16
        ln_k<<<BTc, 256>>>(h, Dc, xnh, Dc, 1, n1s + (long)l * Dc, n1b + (long)l * Dc);

        // Q,K,V = xn @ W^T  (fp16 in/out)
        launch_h(xnh, Dc, wq16 + l * DD, Dc, qh, Dc, BTc, Dc, Dc, 0, 0, 0, 1);
        launch_h(xnh, Dc, wk16 + l * DD, Dc, kh, Dc, BTc, Dc, Dc, 0, 0, 0, 1);
        launch_h(xnh, Dc, wv16 + l * DD, Dc, vh, Dc, BTc, Dc, Dc, 0, 0, 0, 1);

        // fused causal attention (fp16 I/O)
        {
            dim3 fg(Tc / 128, Bc * Hc);
            flash_k<<<fg, 256>>>(qh, kh, vh, ctxh);
        }

        // h = h + ctx @ Wo^T + bo  (fp32 out)
        launch_h(ctxh, Dc, wo16 + l * DD, Dc, h, Dc, BTc, Dc, Dc, bol, h, 0, 0);

        // LN2 -> fp16
        ln_k<<<BTc, 256>>>(h, Dc, xnh, Dc, 1, n2s + (long)l * Dc, n2b + (long)l * Dc);

        // ff = gelu(xn @ W1^T + b1)  (fp16 out)
        launch_h(xnh, Dc, w116 + l * FD, Dc, ffh, DFFc, BTc, DFFc, Dc, b1l, 0, 1, 1);

        // h = h + ff @ W2^T + b2  (fp32 out)
        launch_h(ffh, DFFc, w216 + l * FD, DFFc, h, Dc, BTc, Dc, DFFc, b2l, h, 0, 0);
    }

    // final LN on the 2 last-token rows only -> fp32
    ln_k<<<Bc, 256>>>(h + (long)(Tc - 1) * Dc, TD, fin, Dc, 0, fs, fb);

    // logits (fp32, memory-bound dedicated kernel)
    logits_k<<<(Vc + 7) / 8, 256>>>(fin, Wemb, out);
}

// round 14
// speedup vs baseline: 1.0589x; 1.0589x over previous
#include <cuda_runtime.h>
#include <cuda_bf16.h>
#include <cuda_fp16.h>
#include <math.h>
#include <stdint.h>

// ---------------- problem constants ----------------
#define Bc   2
#define Tc   2048
#define Dc   1024
#define Hc   16
#define HDc  64
#define DFFc 4096
#define Lc   8
#define Vc   50257
#define BTc  (Bc*Tc)          // 4096
#define EPSc 1e-5f

// ---------------- static device scratch (no allocs allowed) ----------------
__device__ float  g_h  [BTc*Dc];
__device__ float  g_fin[Bc*Dc];
__device__ __half g_xnh [BTc*Dc];
__device__ __half g_qkvh[(long)BTc*3*Dc];
__device__ __half g_ctxh[BTc*Dc];
__device__ __half g_ffh [(long)BTc*DFFc];
// fp16 weights (converted once per launch)
__device__ __half g_wqkv16[(long)Lc*3*Dc*Dc];   // packed [L][3][Dc][Dc]
__device__ __half g_wo16[(long)Lc*Dc*Dc];
__device__ __half g_w116[(long)Lc*DFFc*Dc];
__device__ __half g_w216[(long)Lc*DFFc*Dc];

// ---------------- helpers ----------------
__device__ __forceinline__ float gelu_f(float x) {
    const float c = 0.7978845608028654f;
    return 0.5f * x * (1.0f + tanhf(c * (x + 0.044715f * x * x * x)));
}
__device__ __forceinline__ void mma_f16(float* c, const uint32_t* a, const uint32_t* b) {
    asm volatile(
        "mma.sync.aligned.m16n8k16.row.col.f32.f16.f16.f32 "
        "{%0,%1,%2,%3}, {%4,%5,%6,%7}, {%8,%9}, {%0,%1,%2,%3};"
        : "+f"(c[0]), "+f"(c[1]), "+f"(c[2]), "+f"(c[3])
        : "r"(a[0]), "r"(a[1]), "r"(a[2]), "r"(a[3]), "r"(b[0]), "r"(b[1]));
}
__device__ __forceinline__ uint32_t h2pack(float a, float b) {
    __half2 h = __floats2half2_rn(a, b);
    return *(uint32_t*)&h;
}

// ---------------- fp32 -> fp16 conversions (weights, once per launch) -------
__global__ void cvtk(const float* __restrict__ s, __half* __restrict__ d, long n)
{
    long i = ((long)blockIdx.x * blockDim.x + threadIdx.x) * 4;
    if (i >= n) return;
    float4 v = *(const float4*)(s + i);
    uint2 o;
    o.x = h2pack(v.x, v.y);
    o.y = h2pack(v.z, v.w);
    *(uint2*)(d + i) = o;
}
// strided: src [L][per] contiguous -> dst at l*strideDst + off + r
__global__ void cvtk_s(const float* __restrict__ s, __half* __restrict__ d,
                       long n, long per, long strideDst, long off)
{
    long i = ((long)blockIdx.x * blockDim.x + threadIdx.x) * 4;
    if (i >= n) return;
    long l = i / per, r = i % per;
    float4 v = *(const float4*)(s + i);
    uint2 o;
    o.x = h2pack(v.x, v.y);
    o.y = h2pack(v.z, v.w);
    *(uint2*)(d + l * strideDst + off + r) = o;
}

// ---------------- embedding ----------------
__global__ void embed_k(const int* __restrict__ x,
                        const float* __restrict__ Wemb,
                        const float* __restrict__ pos,
                        float* __restrict__ h)
{
    long i = (long)blockIdx.x * blockDim.x + threadIdx.x;
    if (i >= (long)BTc * Dc) return;
    int row = (int)(i / Dc);
    int d   = (int)(i % Dc);
    int t   = row % Tc;
    int tok = x[row];
    h[i] = Wemb[(long)tok * Dc + d] + pos[(long)t * Dc + d];
}

// ---------------- layernorm (ddof=1, std+eps), fp16 or fp32 output ---------
__global__ void ln_k(const float* __restrict__ in, long inStride,
                     void* __restrict__ out, long outStride, int outHalf,
                     const float* __restrict__ sc, const float* __restrict__ sh)
{
    __shared__ float red[256];
    int r = blockIdx.x, tid = threadIdx.x;
    const float* x = in + (long)r * inStride;
    float xv[4];
    float s = 0.f;
#pragma unroll
    for (int i = 0; i < 4; i++) { xv[i] = x[tid + i * 256]; s += xv[i]; }
    red[tid] = s; __syncthreads();
    for (int st = 128; st > 0; st >>= 1) { if (tid < st) red[tid] += red[tid + st]; __syncthreads(); }
    float mean = red[0] * (1.0f / (float)Dc);
    __syncthreads();
    float v = 0.f;
#pragma unroll
    for (int i = 0; i < 4; i++) { float t = xv[i] - mean; v += t * t; }
    red[tid] = v; __syncthreads();
    for (int st = 128; st > 0; st >>= 1) { if (tid < st) red[tid] += red[tid + st]; __syncthreads(); }
    float inv = 1.0f / (sqrtf(red[0] / (float)(Dc - 1)) + EPSc);
#pragma unroll
    for (int i = 0; i < 4; i++) {
        int d = tid + i * 256;
        float o = sc[d] * ((xv[i] - mean) * inv) + sh[d];
        if (outHalf) ((__half*)out)[(long)r * outStride + d] = __float2half_rn(o);
        else         ((float*)out)[(long)r * outStride + d] = o;
    }
}

// =====================================================================
// flash_k (R12-proven, fp16 I/O) with Q/K/V row-stride parameter ld.
// =====================================================================
__global__ __launch_bounds__(256)
void flash_k(const __half* __restrict__ Qg, const __half* __restrict__ Kg,
             const __half* __restrict__ Vg, __half* __restrict__ Og, int ld)
{
    __shared__ uint32_t usm[4608];           // 18432 B
    uint32_t* Qsh = usm;                     // [128][36]
    uint32_t* sKf = usm;                     // [4][8][64] = 8KB
    uint32_t* sVf = usm + 2048;              // [4][8][64] = 8KB

    int qt = (int)gridDim.x - 1 - blockIdx.x;
    int q0 = qt * 128;
    int z  = blockIdx.y;
    int b  = z / Hc, hh = z % Hc;
    long baseQ = (long)b * Tc * ld + (long)hh * HDc;
    const __half* Qb = Qg + baseQ;
    const __half* Kb = Kg + baseQ;
    const __half* Vb = Vg + baseQ;
    __half* Ob = Og + (long)b * Tc * Dc + (long)hh * HDc;

    int tid = threadIdx.x, lane = tid & 31, warp = tid >> 5;
    int g = lane >> 2, c = lane & 3;
    int physC = lane ^ ((lane >> 3) & 3);

    {
        int kr = tid >> 1, half = tid & 1;
        const uint4* src = (const uint4*)(Qb + (long)(q0 + kr) * ld + half * 32);
        uint32_t* dst = Qsh + kr * 36 + half * 16;
#pragma unroll
        for (int f = 0; f < 4; f++)
            *(uint4*)(dst + f * 4) = src[f];
    }
    __syncthreads();

    uint32_t qf[4][4];
    {
        int r0w = warp * 16 + g;
#pragma unroll
        for (int kb = 0; kb < 4; kb++) {
            int w = kb * 8 + c;
            qf[kb][0] = Qsh[r0w * 36 + w];
            qf[kb][1] = Qsh[(r0w + 8) * 36 + w];
            qf[kb][2] = Qsh[r0w * 36 + w + 4];
            qf[kb][3] = Qsh[(r0w + 8) * 36 + w + 4];
        }
    }
    __syncthreads();

    float oacc[8][4];
#pragma unroll
    for (int i = 0; i < 8; i++)
#pragma unroll
        for (int e = 0; e < 4; e++) oacc[i][e] = 0.f;
    float m0 = -1e30f, m1 = -1e30f, l0 = 0.f, l1 = 0.f;

    bool isK = tid < 128;
    int t = isK ? tid : (tid - 128);
    int nK  = t & 63;
    int kqK = t >> 6;
    int nbK = nK >> 3, gK = nK & 7;
    int swzK = (gK >> 1) & 3;
    int nbxK = (nbK & 1) << 3;
    const __half* KpBase = Kb + (long)nK * ld + kqK * 32;
    int kV = t & 63;
    int chV = t >> 6;
    int kbV = kV >> 4, kkV = kV & 15;
    int cV  = (kkV & 7) >> 1, hfV = (kkV >> 3) & 1, loV = kkV & 1;
    const __half* VpBase = Vb + (long)kV * ld + chV * 32;

    int nkt = 2 * qt + 2;
    for (int kt = 0; kt < nkt; kt++) {
        long koff = (long)(kt * 64) * ld;

        if (isK) {
#pragma unroll
            for (int i = 0; i < 2; i++) {
                int kb = 2 * kqK + i;
                const uint4* ps = (const uint4*)(KpBase + koff + i * 16);
                uint4 u0 = ps[0], u1 = ps[1];
                const uint32_t* W0 = (const uint32_t*)&u0;
                const uint32_t* W1 = (const uint32_t*)&u1;
                uint32_t* dst = sKf + kb * 512 + nbK * 64;
#pragma unroll
                for (int cc = 0; cc < 4; cc++) {
                    int s = ((4 * gK + cc) ^ swzK) ^ nbxK;
                    dst[s * 2 + 0] = W0[cc];
                    dst[s * 2 + 1] = W1[cc];
                }
            }
        } else {
            const uint4* vp = (const uint4*)(VpBase + koff);
            uint32_t* dstK = sVf + kbV * 512;
#pragma unroll
            for (int u = 0; u < 4; u++) {
                uint4 vv = vp[u];
                const uint32_t* W = (const uint32_t*)&vv;
#pragma unroll
                for (int w = 0; w < 4; w++) {
                    __half2 h2 = *(__half2*)&W[w];
#pragma unroll
                    for (int hw = 0; hw < 2; hw++) {
                        int j = u * 8 + w * 2 + hw;
                        int n = chV * 32 + j;
                        int nb = n >> 3, gg = n & 7;
                        int s = ((4 * gg + cV) ^ ((gg >> 1) & 3)) ^ ((nb & 1) << 3);
                        __half* hp = (__half*)&dstK[nb * 64 + s * 2 + hfV];
                        hp[loV] = hw ? __high2half(h2) : __low2half(h2);
                    }
                }
            }
        }
        __syncthreads();

        int k0 = kt * 64;
        bool active = (k0 <= q0 + warp * 16 + 15);
        if (active) {
            float sacc[8][4];
#pragma unroll
            for (int i = 0; i < 8; i++)
#pragma unroll
                for (int e = 0; e < 4; e++) sacc[i][e] = 0.f;
#pragma unroll
            for (int kb = 0; kb < 4; kb++) {
#pragma unroll
                for (int nb = 0; nb < 8; nb++) {
                    uint2 bk = *(uint2*)&sKf[kb * 512 + nb * 64 +
                                             (physC ^ ((nb & 1) << 3)) * 2];
                    mma_f16(sacc[nb], qf[kb], &bk.x);
                }
            }

            int qr0 = q0 + warp * 16 + g;
            int qr1 = qr0 + 8;
            bool maskNeed = (k0 + 63 > q0 + warp * 16);
            float rm0 = -1e30f, rm1 = -1e30f;
#pragma unroll
            for (int ni = 0; ni < 8; ni++) {
#pragma unroll
                for (int e = 0; e < 4; e++) {
                    float vvv = sacc[ni][e] * 0.125f;
                    if (maskNeed) {
                        int kc = k0 + ni * 8 + c * 2 + (e & 1);
                        if (kc > ((e >= 2) ? qr1 : qr0)) vvv = -1e30f;
                    }
                    sacc[ni][e] = vvv;
                    if (e < 2) rm0 = fmaxf(rm0, vvv); else rm1 = fmaxf(rm1, vvv);
                }
            }
            rm0 = fmaxf(rm0, __shfl_xor_sync(0xffffffffu, rm0, 1));
            rm0 = fmaxf(rm0, __shfl_xor_sync(0xffffffffu, rm0, 2));
            rm1 = fmaxf(rm1, __shfl_xor_sync(0xffffffffu, rm1, 1));
            rm1 = fmaxf(rm1, __shfl_xor_sync(0xffffffffu, rm1, 2));
            float mn0 = fmaxf(m0, rm0), mn1 = fmaxf(m1, rm1);
            float sc0 = __expf(m0 - mn0), sc1 = __expf(m1 - mn1);
            float rs0 = 0.f, rs1 = 0.f;
#pragma unroll
            for (int ni = 0; ni < 8; ni++) {
#pragma unroll
                for (int e = 0; e < 4; e++) {
                    float ee = __expf(sacc[ni][e] - ((e < 2) ? mn0 : mn1));
                    sacc[ni][e] = ee;
                    if (e < 2) rs0 += ee; else rs1 += ee;
                }
            }
            rs0 += __shfl_xor_sync(0xffffffffu, rs0, 1);
            rs0 += __shfl_xor_sync(0xffffffffu, rs0, 2);
            rs1 += __shfl_xor_sync(0xffffffffu, rs1, 1);
            rs1 += __shfl_xor_sync(0xffffffffu, rs1, 2);
            l0 = l0 * sc0 + rs0;
            l1 = l1 * sc1 + rs1;
            m0 = mn0; m1 = mn1;
#pragma unroll
            for (int ni = 0; ni < 8; ni++) {
#pragma unroll
                for (int e = 0; e < 4; e++) oacc[ni][e] *= (e < 2) ? sc0 : sc1;
            }

#pragma unroll
            for (int kb = 0; kb < 4; kb++) {
                uint32_t pf[4];
                pf[0] = h2pack(sacc[2 * kb][0],     sacc[2 * kb][1]);
                pf[1] = h2pack(sacc[2 * kb][2],     sacc[2 * kb][3]);
                pf[2] = h2pack(sacc[2 * kb + 1][0], sacc[2 * kb + 1][1]);
                pf[3] = h2pack(sacc[2 * kb + 1][2], sacc[2 * kb + 1][3]);
#pragma unroll
                for (int nb = 0; nb < 8; nb++) {
                    uint2 bv = *(uint2*)&sVf[kb * 512 + nb * 64 +
                                             (physC ^ ((nb & 1) << 3)) * 2];
                    mma_f16(oacc[nb], pf, &bv.x);
                }
            }
        }
        __syncthreads();
    }

    float il0 = 1.f / l0, il1 = 1.f / l1;
    int r0 = q0 + warp * 16 + g;
#pragma unroll
    for (int ni = 0; ni < 8; ni++) {
        int d = ni * 8 + 2 * c;
        *(uint32_t*)(Ob + (long)r0 * Dc + d) =
            h2pack(oacc[ni][0] * il0, oacc[ni][1] * il0);
        *(uint32_t*)(Ob + (long)(r0 + 8) * Dc + d) =
            h2pack(oacc[ni][2] * il1, oacc[ni][3] * il1);
    }
}

// =====================================================================
// gemm_h (R12 shape, BK=32): dense NT GEMM, fp16 operands, fp32 accum.
// 128x128 block, 8 warps of 64x32 tiles, 2 CTA/SM.
// BK=32 = two 16-K sub-tiles per __syncthreads.
// Requires M,N multiples of 128, K multiple of 32.
// =====================================================================
#define BM 128
#define BN 128

__global__ __launch_bounds__(256, 2)
void gemm_h(const __half* __restrict__ A, int lda,
            const __half* __restrict__ B, int ldb,
            void* __restrict__ Cp, int ldc, int K,
            const float* __restrict__ bias,
            const float* __restrict__ resid, int doGelu, int outHalf)
{
    __shared__ uint32_t sAx[2][2][8][128];   // [stage][sub][mblock][...]
    __shared__ uint32_t sBx[2][2][16][64];

    int m0 = blockIdx.y * BM, n0 = blockIdx.x * BN;
    int tid = threadIdx.x, lane = tid & 31, warp = tid >> 5;
    int wm = (warp & 1) * 64, wn = (warp >> 1) * 32;
    int bA0 = wm >> 4, nb0 = wn >> 3;

    float acc[4][4][4];
#pragma unroll
    for (int i = 0; i < 4; i++)
#pragma unroll
        for (int jx = 0; jx < 4; jx++)
#pragma unroll
            for (int e = 0; e < 4; e++) acc[i][jx][e] = 0.f;

    int r  = tid >> 1, hf = tid & 1;
    int j  = r >> 4, nb = r >> 3, g = r & 7, hi = (r >> 3) & 1;
    int swzA = (g >> 1) & 3;
    int nbx  = (nb & 1) << 3;
    const __half* Ap = A + (long)(m0 + r) * lda + hf * 8;
    const __half* Bp = B + (long)(n0 + r) * ldb + hf * 8;

    int nIter = K / 32;

    uint4 pa[2], pb[2];
    pa[0] = *(const uint4*)Ap;        pa[1] = *(const uint4*)(Ap + 16);
    pb[0] = *(const uint4*)Bp;        pb[1] = *(const uint4*)(Bp + 16);

#pragma unroll
    for (int s2 = 0; s2 < 2; s2++) {
        const uint32_t* WA = (const uint32_t*)&pa[s2];
        const uint32_t* WB = (const uint32_t*)&pb[s2];
        uint32_t* aw = sAx[0][s2][j];
        uint32_t* bw = sBx[0][s2][nb];
#pragma unroll
        for (int c = 0; c < 4; c++) {
            int ph = (4 * g + c) ^ swzA;
            aw[ph * 4 + hi + 2 * hf] = WA[c];
            bw[(ph ^ nbx) * 2 + hf]  = WB[c];
        }
    }
    __syncthreads();

    int physC = lane ^ ((lane >> 3) & 3);

    for (int it = 0; it < nIter; it++) {
        int cur = it & 1;
        bool more = (it + 1) < nIter;
        if (more) {
            long ko = (long)(it + 1) * 32;
            pa[0] = *(const uint4*)(Ap + ko);      pa[1] = *(const uint4*)(Ap + ko + 16);
            pb[0] = *(const uint4*)(Bp + ko);      pb[1] = *(const uint4*)(Bp + ko + 16);
        }

#pragma unroll
        for (int s2 = 0; s2 < 2; s2++) {
            float4 af[4]; float2 bf[4];
#pragma unroll
            for (int mi = 0; mi < 4; mi++)
                af[mi] = ((const float4*)sAx[cur][s2][bA0 + mi])[physC];
#pragma unroll
            for (int ni = 0; ni < 4; ni++) {
                int nb2 = nb0 + ni;
                bf[ni] = ((const float2*)sBx[cur][s2][nb2])[physC ^ ((nb2 & 1) << 3)];
            }
#pragma unroll
            for (int mi = 0; mi < 4; mi++)
#pragma unroll
                for (int ni = 0; ni < 4; ni++)
                    mma_f16(acc[mi][ni], (const uint32_t*)&af[mi], (const uint32_t*)&bf[ni]);
        }

        if (more) {
            int nxt = cur ^ 1;
#pragma unroll
            for (int s2 = 0; s2 < 2; s2++) {
                const uint32_t* WA = (const uint32_t*)&pa[s2];
                const uint32_t* WB = (const uint32_t*)&pb[s2];
                uint32_t* aw = sAx[nxt][s2][j];
                uint32_t* bw = sBx[nxt][s2][nb];
#pragma unroll
                for (int c = 0; c < 4; c++) {
                    int ph = (4 * g + c) ^ swzA;
                    aw[ph * 4 + hi + 2 * hf] = WA[c];
                    bw[(ph ^ nbx) * 2 + hf]  = WB[c];
                }
            }
        }
        __syncthreads();
    }

    // ---- epilogue ----
    int ge = lane >> 2, c2 = (lane & 3) * 2;
#pragma unroll
    for (int mi = 0; mi < 4; mi++) {
#pragma unroll
        for (int ni = 0; ni < 4; ni++) {
            int gm = m0 + wm + mi * 16 + ge;
            int gn = n0 + wn + ni * 8 + c2;
            float v0 = acc[mi][ni][0], v1 = acc[mi][ni][1];
            float v2 = acc[mi][ni][2], v3 = acc[mi][ni][3];
            if (bias) {
                float b0 = bias[gn], b1 = bias[gn + 1];
                v0 += b0; v1 += b1; v2 += b0; v3 += b1;
            }
            if (doGelu) { v0 = gelu_f(v0); v1 = gelu_f(v1); v2 = gelu_f(v2); v3 = gelu_f(v3); }
            if (resid) {
                const float* r0p = resid + (long)gm * ldc + gn;
                const float* r1p = resid + (long)(gm + 8) * ldc + gn;
                v0 += r0p[0]; v1 += r0p[1]; v2 += r1p[0]; v3 += r1p[1];
            }
            if (outHalf) {
                __half* C = (__half*)Cp;
                *(uint32_t*)(C + (long)gm * ldc + gn)       = h2pack(v0, v1);
                *(uint32_t*)(C + (long)(gm + 8) * ldc + gn) = h2pack(v2, v3);
            } else {
                float* C = (float*)Cp;
                *(float2*)(C + (long)gm * ldc + gn)       = make_float2(v0, v1);
                *(float2*)(C + (long)(gm + 8) * ldc + gn) = make_float2(v2, v3);
            }
        }
    }
}

// ---------------- dedicated logits kernel (M=2, fp32, memory-bound) ----------
__global__ __launch_bounds__(256)
void logits_k(const float* __restrict__ fin,
              const float* __restrict__ Wemb,
              float* __restrict__ out)
{
    __shared__ float f0[Dc], f1[Dc];
    int tid = threadIdx.x;
    for (int i = tid; i < Dc; i += 256) { f0[i] = fin[i]; f1[i] = fin[Dc + i]; }
    __syncthreads();
    int warp = tid >> 5, lane = tid & 31;
    long v = (long)blockIdx.x * 8 + warp;
    if (v >= Vc) return;
    const float* w = Wemb + v * Dc;
    float d0 = 0.f, d1 = 0.f;
    for (int i = lane * 4; i < Dc; i += 128) {
        float4 wv = *(const float4*)(w + i);
        d0 += wv.x * f0[i] + wv.y * f0[i+1] + wv.z * f0[i+2] + wv.w * f0[i+3];
        d1 += wv.x * f1[i] + wv.y * f1[i+1] + wv.z * f1[i+2] + wv.w * f1[i+3];
    }
#pragma unroll
    for (int o = 16; o > 0; o >>= 1) {
        d0 += __shfl_xor_sync(0xffffffff, d0, o);
        d1 += __shfl_xor_sync(0xffffffff, d1, o);
    }
    if (lane == 0) { out[v] = d0; out[(long)Vc + v] = d1; }
}

// ---------------- host-side launch helpers ----------------
static inline void launch_h(const __half* A, int lda, const __half* B, int ldb,
                            void* C, int ldc, int M, int N, int K,
                            const float* bias, const float* resid,
                            int gelu, int outHalf)
{
    dim3 g(N / BN, M / BM, 1);
    gemm_h<<<g, 256>>>(A, lda, B, ldb, C, ldc, K, bias, resid, gelu, outHalf);
}
static inline void launch_cvt(const float* s, __half* d, long n)
{
    long blocks = (n / 4 + 255) / 256;
    cvtk<<<(unsigned)blocks, 256>>>(s, d, n);
}
static inline void launch_cvt_s(const float* s, __half* d, long n,
                                long per, long strideDst, long off)
{
    long blocks = (n / 4 + 255) / 256;
    cvtk_s<<<(unsigned)blocks, 256>>>(s, d, n, per, strideDst, off);
}

extern "C" void kernel_launch(void* const* d_in, const int* in_sizes, int n_in,
                              void* d_out, int out_size)
{
    const int*   x    = (const int*)  d_in[0];
    const float* Wemb = (const float*)d_in[1];
    const float* pos  = (const float*)d_in[2];
    const float* Wq   = (const float*)d_in[3];
    const float* Wk   = (const float*)d_in[4];
    const float* Wv   = (const float*)d_in[5];
    const float* Wo   = (const float*)d_in[6];
    const float* bo   = (const float*)d_in[7];
    const float* n1s  = (const float*)d_in[8];
    const float* n1b  = (const float*)d_in[9];
    const float* n2s  = (const float*)d_in[10];
    const float* n2b  = (const float*)d_in[11];
    const float* W1   = (const float*)d_in[12];
    const float* b1   = (const float*)d_in[13];
    const float* W2   = (const float*)d_in[14];
    const float* b2   = (const float*)d_in[15];
    const float* fs   = (const float*)d_in[16];
    const float* fb   = (const float*)d_in[17];
    float* out = (float*)d_out;

    float  *h, *fin;
    __half *xnh, *qkvh, *ctxh, *ffh;
    __half *wqkv16, *wo16, *w116, *w216;
    cudaGetSymbolAddress((void**)&h,     g_h);
    cudaGetSymbolAddress((void**)&fin,   g_fin);
    cudaGetSymbolAddress((void**)&xnh,   g_xnh);
    cudaGetSymbolAddress((void**)&qkvh,  g_qkvh);
    cudaGetSymbolAddress((void**)&ctxh,  g_ctxh);
    cudaGetSymbolAddress((void**)&ffh,   g_ffh);
    cudaGetSymbolAddress((void**)&wqkv16,g_wqkv16);
    cudaGetSymbolAddress((void**)&wo16,  g_wo16);
    cudaGetSymbolAddress((void**)&w116,  g_w116);
    cudaGetSymbolAddress((void**)&w216,  g_w216);

    const long TD = (long)Tc * Dc;
    const long DD = (long)Dc * Dc;
    const long FD = (long)DFFc * Dc;
    const int  D3 = 3 * Dc;

    // weights -> fp16 (once per launch; graph-capturable)
    launch_cvt_s(Wq, wqkv16, (long)Lc * DD, DD, 3 * DD, 0);
    launch_cvt_s(Wk, wqkv16, (long)Lc * DD, DD, 3 * DD, DD);
    launch_cvt_s(Wv, wqkv16, (long)Lc * DD, DD, 3 * DD, 2 * DD);
    launch_cvt(Wo, wo16, (long)Lc * DD);
    launch_cvt(W1, w116, (long)Lc * FD);
    launch_cvt(W2, w216, (long)Lc * FD);

    {
        long n = (long)BTc * Dc;
        embed_k<<<(unsigned)((n + 255) / 256), 256>>>(x, Wemb, pos, h);
    }

    for (int l = 0; l < Lc; l++) {
        const float* bol = bo + (long)l * Dc;
        const float* b1l = b1 + (long)l * DFFc;
        const float* b2l = b2 + (long)l * Dc;

        // LN1 -> fp16
        ln_k<<<BTc, 256>>>(h, Dc, xnh, Dc, 1, n1s + (long)l * Dc, n1b + (long)l * Dc);

        // QKV = xn @ Wqkv^T  (fused, fp16 in/out, N=3072)
        launch_h(xnh, Dc, wqkv16 + (long)l * 3 * DD, Dc, qkvh, D3,
                 BTc, D3, Dc, 0, 0, 0, 1);

        // fused causal attention (fp16 I/O, QKV row stride 3*Dc)
        {
            dim3 fg(Tc / 128, Bc * Hc);
            flash_k<<<fg, 256>>>(qkvh, qkvh + Dc, qkvh + 2 * Dc, ctxh, D3);
        }

        // h = h + ctx @ Wo^T + bo  (fp32 out)
        launch_h(ctxh, Dc, wo16 + (long)l * DD, Dc, h, Dc, BTc, Dc, Dc, bol, h, 0, 0);

        // LN2 -> fp16
        ln_k<<<BTc, 256>>>(h, Dc, xnh, Dc, 1, n2s + (long)l * Dc, n2b + (long)l * Dc);

        // ff = gelu(xn @ W1^T + b1)  (fp16 out)
        launch_h(xnh, Dc, w116 + (long)l * FD, Dc, ffh, DFFc, BTc, DFFc, Dc, b1l, 0, 1, 1);

        // h = h + ff @ W2^T + b2  (fp32 out)
        launch_h(ffh, DFFc, w216 + (long)l * FD, DFFc, h, Dc, BTc, Dc, DFFc, b2l, h, 0, 0);
    }

    // final LN on the 2 last-token rows only -> fp32
    ln_k<<<Bc, 256>>>(h + (long)(Tc - 1) * Dc, TD, fin, Dc, 0, fs, fb);

    // logits (fp32, memory-bound dedicated kernel)
    logits_k<<<(Vc + 7) / 8, 256>>>(fin, Wemb, out);
}

// round 15
// speedup vs baseline: 1.1278x; 1.0651x over previous
#include <cuda_runtime.h>
#include <cuda_bf16.h>
#include <cuda_fp16.h>
#include <math.h>
#include <stdint.h>

// ---------------- problem constants ----------------
#define Bc   2
#define Tc   2048
#define Dc   1024
#define Hc   16
#define HDc  64
#define DFFc 4096
#define Lc   8
#define Vc   50257
#define BTc  (Bc*Tc)          // 4096
#define EPSc 1e-5f

// ---------------- static device scratch (no allocs allowed) ----------------
__device__ float  g_h  [BTc*Dc];
__device__ float  g_fin[Bc*Dc];
__device__ __half g_xnh [BTc*Dc];
__device__ __half g_qkvh[(long)BTc*3*Dc];
__device__ __half g_ctxh[BTc*Dc];
__device__ __half g_ffh [(long)BTc*DFFc];
// fp16 weights (converted once per launch)
__device__ __half g_wqkv16[(long)Lc*3*Dc*Dc];   // packed [L][3][Dc][Dc]
__device__ __half g_wo16[(long)Lc*Dc*Dc];
__device__ __half g_w116[(long)Lc*DFFc*Dc];
__device__ __half g_w216[(long)Lc*DFFc*Dc];

// ---------------- helpers ----------------
__device__ __forceinline__ float gelu_f(float x) {
    const float c = 0.7978845608028654f;
    return 0.5f * x * (1.0f + tanhf(c * (x + 0.044715f * x * x * x)));
}
__device__ __forceinline__ void mma_f16(float* c, const uint32_t* a, const uint32_t* b) {
    asm volatile(
        "mma.sync.aligned.m16n8k16.row.col.f32.f16.f16.f32 "
        "{%0,%1,%2,%3}, {%4,%5,%6,%7}, {%8,%9}, {%0,%1,%2,%3};"
        : "+f"(c[0]), "+f"(c[1]), "+f"(c[2]), "+f"(c[3])
        : "r"(a[0]), "r"(a[1]), "r"(a[2]), "r"(a[3]), "r"(b[0]), "r"(b[1]));
}
__device__ __forceinline__ uint32_t h2pack(float a, float b) {
    __half2 h = __floats2half2_rn(a, b);
    return *(uint32_t*)&h;
}

// ---------------- fp32 -> fp16 conversions (weights, once per launch) -------
__global__ void cvtk(const float* __restrict__ s, __half* __restrict__ d, long n)
{
    long i = ((long)blockIdx.x * blockDim.x + threadIdx.x) * 4;
    if (i >= n) return;
    float4 v = *(const float4*)(s + i);
    uint2 o;
    o.x = h2pack(v.x, v.y);
    o.y = h2pack(v.z, v.w);
    *(uint2*)(d + i) = o;
}
// strided: src [L][per] contiguous -> dst at l*strideDst + off + r
__global__ void cvtk_s(const float* __restrict__ s, __half* __restrict__ d,
                       long n, long per, long strideDst, long off)
{
    long i = ((long)blockIdx.x * blockDim.x + threadIdx.x) * 4;
    if (i >= n) return;
    long l = i / per, r = i % per;
    float4 v = *(const float4*)(s + i);
    uint2 o;
    o.x = h2pack(v.x, v.y);
    o.y = h2pack(v.z, v.w);
    *(uint2*)(d + l * strideDst + off + r) = o;
}

// ---------------- embedding ----------------
__global__ void embed_k(const int* __restrict__ x,
                        const float* __restrict__ Wemb,
                        const float* __restrict__ pos,
                        float* __restrict__ h)
{
    long i = (long)blockIdx.x * blockDim.x + threadIdx.x;
    if (i >= (long)BTc * Dc) return;
    int row = (int)(i / Dc);
    int d   = (int)(i % Dc);
    int t   = row % Tc;
    int tok = x[row];
    h[i] = Wemb[(long)tok * Dc + d] + pos[(long)t * Dc + d];
}

// ---------------- layernorm (ddof=1, std+eps), fp16 or fp32 output ---------
__global__ void ln_k(const float* __restrict__ in, long inStride,
                     void* __restrict__ out, long outStride, int outHalf,
                     const float* __restrict__ sc, const float* __restrict__ sh)
{
    __shared__ float red[256];
    int r = blockIdx.x, tid = threadIdx.x;
    const float* x = in + (long)r * inStride;
    float xv[4];
    float s = 0.f;
#pragma unroll
    for (int i = 0; i < 4; i++) { xv[i] = x[tid + i * 256]; s += xv[i]; }
    red[tid] = s; __syncthreads();
    for (int st = 128; st > 0; st >>= 1) { if (tid < st) red[tid] += red[tid + st]; __syncthreads(); }
    float mean = red[0] * (1.0f / (float)Dc);
    __syncthreads();
    float v = 0.f;
#pragma unroll
    for (int i = 0; i < 4; i++) { float t = xv[i] - mean; v += t * t; }
    red[tid] = v; __syncthreads();
    for (int st = 128; st > 0; st >>= 1) { if (tid < st) red[tid] += red[tid + st]; __syncthreads(); }
    float inv = 1.0f / (sqrtf(red[0] / (float)(Dc - 1)) + EPSc);
#pragma unroll
    for (int i = 0; i < 4; i++) {
        int d = tid + i * 256;
        float o = sc[d] * ((xv[i] - mean) * inv) + sh[d];
        if (outHalf) ((__half*)out)[(long)r * outStride + d] = __float2half_rn(o);
        else         ((float*)out)[(long)r * outStride + d] = o;
    }
}

// =====================================================================
// flash_k (R12-proven, fp16 I/O) with Q/K/V row-stride parameter ld.
// =====================================================================
__global__ __launch_bounds__(256)
void flash_k(const __half* __restrict__ Qg, const __half* __restrict__ Kg,
             const __half* __restrict__ Vg, __half* __restrict__ Og, int ld)
{
    __shared__ uint32_t usm[4608];           // 18432 B
    uint32_t* Qsh = usm;                     // [128][36]
    uint32_t* sKf = usm;                     // [4][8][64] = 8KB
    uint32_t* sVf = usm + 2048;              // [4][8][64] = 8KB

    int qt = (int)gridDim.x - 1 - blockIdx.x;
    int q0 = qt * 128;
    int z  = blockIdx.y;
    int b  = z / Hc, hh = z % Hc;
    long baseQ = (long)b * Tc * ld + (long)hh * HDc;
    const __half* Qb = Qg + baseQ;
    const __half* Kb = Kg + baseQ;
    const __half* Vb = Vg + baseQ;
    __half* Ob = Og + (long)b * Tc * Dc + (long)hh * HDc;

    int tid = threadIdx.x, lane = tid & 31, warp = tid >> 5;
    int g = lane >> 2, c = lane & 3;
    int physC = lane ^ ((lane >> 3) & 3);

    {
        int kr = tid >> 1, half = tid & 1;
        const uint4* src = (const uint4*)(Qb + (long)(q0 + kr) * ld + half * 32);
        uint32_t* dst = Qsh + kr * 36 + half * 16;
#pragma unroll
        for (int f = 0; f < 4; f++)
            *(uint4*)(dst + f * 4) = src[f];
    }
    __syncthreads();

    uint32_t qf[4][4];
    {
        int r0w = warp * 16 + g;
#pragma unroll
        for (int kb = 0; kb < 4; kb++) {
            int w = kb * 8 + c;
            qf[kb][0] = Qsh[r0w * 36 + w];
            qf[kb][1] = Qsh[(r0w + 8) * 36 + w];
            qf[kb][2] = Qsh[r0w * 36 + w + 4];
            qf[kb][3] = Qsh[(r0w + 8) * 36 + w + 4];
        }
    }
    __syncthreads();

    float oacc[8][4];
#pragma unroll
    for (int i = 0; i < 8; i++)
#pragma unroll
        for (int e = 0; e < 4; e++) oacc[i][e] = 0.f;
    float m0 = -1e30f, m1 = -1e30f, l0 = 0.f, l1 = 0.f;

    bool isK = tid < 128;
    int t = isK ? tid : (tid - 128);
    int nK  = t & 63;
    int kqK = t >> 6;
    int nbK = nK >> 3, gK = nK & 7;
    int swzK = (gK >> 1) & 3;
    int nbxK = (nbK & 1) << 3;
    const __half* KpBase = Kb + (long)nK * ld + kqK * 32;
    int kV = t & 63;
    int chV = t >> 6;
    int kbV = kV >> 4, kkV = kV & 15;
    int cV  = (kkV & 7) >> 1, hfV = (kkV >> 3) & 1, loV = kkV & 1;
    const __half* VpBase = Vb + (long)kV * ld + chV * 32;

    int nkt = 2 * qt + 2;
    for (int kt = 0; kt < nkt; kt++) {
        long koff = (long)(kt * 64) * ld;

        if (isK) {
#pragma unroll
            for (int i = 0; i < 2; i++) {
                int kb = 2 * kqK + i;
                const uint4* ps = (const uint4*)(KpBase + koff + i * 16);
                uint4 u0 = ps[0], u1 = ps[1];
                const uint32_t* W0 = (const uint32_t*)&u0;
                const uint32_t* W1 = (const uint32_t*)&u1;
                uint32_t* dst = sKf + kb * 512 + nbK * 64;
#pragma unroll
                for (int cc = 0; cc < 4; cc++) {
                    int s = ((4 * gK + cc) ^ swzK) ^ nbxK;
                    dst[s * 2 + 0] = W0[cc];
                    dst[s * 2 + 1] = W1[cc];
                }
            }
        } else {
            const uint4* vp = (const uint4*)(VpBase + koff);
            uint32_t* dstK = sVf + kbV * 512;
#pragma unroll
            for (int u = 0; u < 4; u++) {
                uint4 vv = vp[u];
                const uint32_t* W = (const uint32_t*)&vv;
#pragma unroll
                for (int w = 0; w < 4; w++) {
                    __half2 h2 = *(__half2*)&W[w];
#pragma unroll
                    for (int hw = 0; hw < 2; hw++) {
                        int j = u * 8 + w * 2 + hw;
                        int n = chV * 32 + j;
                        int nb = n >> 3, gg = n & 7;
                        int s = ((4 * gg + cV) ^ ((gg >> 1) & 3)) ^ ((nb & 1) << 3);
                        __half* hp = (__half*)&dstK[nb * 64 + s * 2 + hfV];
                        hp[loV] = hw ? __high2half(h2) : __low2half(h2);
                    }
                }
            }
        }
        __syncthreads();

        int k0 = kt * 64;
        bool active = (k0 <= q0 + warp * 16 + 15);
        if (active) {
            float sacc[8][4];
#pragma unroll
            for (int i = 0; i < 8; i++)
#pragma unroll
                for (int e = 0; e < 4; e++) sacc[i][e] = 0.f;
#pragma unroll
            for (int kb = 0; kb < 4; kb++) {
#pragma unroll
                for (int nb = 0; nb < 8; nb++) {
                    uint2 bk = *(uint2*)&sKf[kb * 512 + nb * 64 +
                                             (physC ^ ((nb & 1) << 3)) * 2];
                    mma_f16(sacc[nb], qf[kb], &bk.x);
                }
            }

            int qr0 = q0 + warp * 16 + g;
            int qr1 = qr0 + 8;
            bool maskNeed = (k0 + 63 > q0 + warp * 16);
            float rm0 = -1e30f, rm1 = -1e30f;
#pragma unroll
            for (int ni = 0; ni < 8; ni++) {
#pragma unroll
                for (int e = 0; e < 4; e++) {
                    float vvv = sacc[ni][e] * 0.125f;
                    if (maskNeed) {
                        int kc = k0 + ni * 8 + c * 2 + (e & 1);
                        if (kc > ((e >= 2) ? qr1 : qr0)) vvv = -1e30f;
                    }
                    sacc[ni][e] = vvv;
                    if (e < 2) rm0 = fmaxf(rm0, vvv); else rm1 = fmaxf(rm1, vvv);
                }
            }
            rm0 = fmaxf(rm0, __shfl_xor_sync(0xffffffffu, rm0, 1));
            rm0 = fmaxf(rm0, __shfl_xor_sync(0xffffffffu, rm0, 2));
            rm1 = fmaxf(rm1, __shfl_xor_sync(0xffffffffu, rm1, 1));
            rm1 = fmaxf(rm1, __shfl_xor_sync(0xffffffffu, rm1, 2));
            float mn0 = fmaxf(m0, rm0), mn1 = fmaxf(m1, rm1);
            float sc0 = __expf(m0 - mn0), sc1 = __expf(m1 - mn1);
            float rs0 = 0.f, rs1 = 0.f;
#pragma unroll
            for (int ni = 0; ni < 8; ni++) {
#pragma unroll
                for (int e = 0; e < 4; e++) {
                    float ee = __expf(sacc[ni][e] - ((e < 2) ? mn0 : mn1));
                    sacc[ni][e] = ee;
                    if (e < 2) rs0 += ee; else rs1 += ee;
                }
            }
            rs0 += __shfl_xor_sync(0xffffffffu, rs0, 1);
            rs0 += __shfl_xor_sync(0xffffffffu, rs0, 2);
            rs1 += __shfl_xor_sync(0xffffffffu, rs1, 1);
            rs1 += __shfl_xor_sync(0xffffffffu, rs1, 2);
            l0 = l0 * sc0 + rs0;
            l1 = l1 * sc1 + rs1;
            m0 = mn0; m1 = mn1;
#pragma unroll
            for (int ni = 0; ni < 8; ni++) {
#pragma unroll
                for (int e = 0; e < 4; e++) oacc[ni][e] *= (e < 2) ? sc0 : sc1;
            }

#pragma unroll
            for (int kb = 0; kb < 4; kb++) {
                uint32_t pf[4];
                pf[0] = h2pack(sacc[2 * kb][0],     sacc[2 * kb][1]);
                pf[1] = h2pack(sacc[2 * kb][2],     sacc[2 * kb][3]);
                pf[2] = h2pack(sacc[2 * kb + 1][0], sacc[2 * kb + 1][1]);
                pf[3] = h2pack(sacc[2 * kb + 1][2], sacc[2 * kb + 1][3]);
#pragma unroll
                for (int nb = 0; nb < 8; nb++) {
                    uint2 bv = *(uint2*)&sVf[kb * 512 + nb * 64 +
                                             (physC ^ ((nb & 1) << 3)) * 2];
                    mma_f16(oacc[nb], pf, &bv.x);
                }
            }
        }
        __syncthreads();
    }

    float il0 = 1.f / l0, il1 = 1.f / l1;
    int r0 = q0 + warp * 16 + g;
#pragma unroll
    for (int ni = 0; ni < 8; ni++) {
        int d = ni * 8 + 2 * c;
        *(uint32_t*)(Ob + (long)r0 * Dc + d) =
            h2pack(oacc[ni][0] * il0, oacc[ni][1] * il0);
        *(uint32_t*)(Ob + (long)(r0 + 8) * Dc + d) =
            h2pack(oacc[ni][2] * il1, oacc[ni][3] * il1);
    }
}

// =====================================================================
// gemm_h (R12 verbatim): dense NT GEMM, fp16 operands, fp32 accum.
// 128x128 block, 8 warps of 64x32 tiles, BK=16, 2 CTA/SM, 128 regs.
// =====================================================================
#define BM 128
#define BN 128

__global__ __launch_bounds__(256, 2)
void gemm_h(const __half* __restrict__ A, int lda,
            const __half* __restrict__ B, int ldb,
            void* __restrict__ Cp, int ldc, int K,
            const float* __restrict__ bias,
            const float* __restrict__ resid, int doGelu, int outHalf)
{
    __shared__ uint32_t sAx[2][8][128];
    __shared__ uint32_t sBx[2][16][64];

    int m0 = blockIdx.y * BM, n0 = blockIdx.x * BN;
    int tid = threadIdx.x, lane = tid & 31, warp = tid >> 5;
    int wm = (warp & 1) * 64, wn = (warp >> 1) * 32;
    int bA0 = wm >> 4, nb0 = wn >> 3;

    float acc[4][4][4];
#pragma unroll
    for (int i = 0; i < 4; i++)
#pragma unroll
        for (int jx = 0; jx < 4; jx++)
#pragma unroll
            for (int e = 0; e < 4; e++) acc[i][jx][e] = 0.f;

    int r  = tid >> 1, hf = tid & 1;
    int j  = r >> 4, nb = r >> 3, g = r & 7, hi = (r >> 3) & 1;
    int swzA = (g >> 1) & 3;
    int nbx  = (nb & 1) << 3;
    const __half* Ap = A + (long)(m0 + r) * lda + hf * 8;
    const __half* Bp = B + (long)(n0 + r) * ldb + hf * 8;

    int nIter = K / 16;

    uint4 pa = *(const uint4*)Ap;
    uint4 pb = *(const uint4*)Bp;

    {
        const uint32_t* WA = (const uint32_t*)&pa;
        const uint32_t* WB = (const uint32_t*)&pb;
        uint32_t* aw = sAx[0][j];
        uint32_t* bw = sBx[0][nb];
#pragma unroll
        for (int c = 0; c < 4; c++) {
            int ph = (4 * g + c) ^ swzA;
            aw[ph * 4 + hi + 2 * hf] = WA[c];
            bw[(ph ^ nbx) * 2 + hf]  = WB[c];
        }
    }
    __syncthreads();

    int physC = lane ^ ((lane >> 3) & 3);

    for (int it = 0; it < nIter; it++) {
        int cur = it & 1;
        bool more = (it + 1) < nIter;
        if (more) {
            long ko = (long)(it + 1) * 16;
            pa = *(const uint4*)(Ap + ko);
            pb = *(const uint4*)(Bp + ko);
        }

        {
            float4 af[4]; float2 bf[4];
#pragma unroll
            for (int mi = 0; mi < 4; mi++)
                af[mi] = ((const float4*)sAx[cur][bA0 + mi])[physC];
#pragma unroll
            for (int ni = 0; ni < 4; ni++) {
                int nb2 = nb0 + ni;
                bf[ni] = ((const float2*)sBx[cur][nb2])[physC ^ ((nb2 & 1) << 3)];
            }
#pragma unroll
            for (int mi = 0; mi < 4; mi++)
#pragma unroll
                for (int ni = 0; ni < 4; ni++)
                    mma_f16(acc[mi][ni], (const uint32_t*)&af[mi], (const uint32_t*)&bf[ni]);
        }

        if (more) {
            int nxt = cur ^ 1;
            const uint32_t* WA = (const uint32_t*)&pa;
            const uint32_t* WB = (const uint32_t*)&pb;
            uint32_t* aw = sAx[nxt][j];
            uint32_t* bw = sBx[nxt][nb];
#pragma unroll
            for (int c = 0; c < 4; c++) {
                int ph = (4 * g + c) ^ swzA;
                aw[ph * 4 + hi + 2 * hf] = WA[c];
                bw[(ph ^ nbx) * 2 + hf]  = WB[c];
            }
        }
        __syncthreads();
    }

    int ge = lane >> 2, c2 = (lane & 3) * 2;
#pragma unroll
    for (int mi = 0; mi < 4; mi++) {
#pragma unroll
        for (int ni = 0; ni < 4; ni++) {
            int gm = m0 + wm + mi * 16 + ge;
            int gn = n0 + wn + ni * 8 + c2;
            float v0 = acc[mi][ni][0], v1 = acc[mi][ni][1];
            float v2 = acc[mi][ni][2], v3 = acc[mi][ni][3];
            if (bias) {
                float b0 = bias[gn], b1 = bias[gn + 1];
                v0 += b0; v1 += b1; v2 += b0; v3 += b1;
            }
            if (doGelu) { v0 = gelu_f(v0); v1 = gelu_f(v1); v2 = gelu_f(v2); v3 = gelu_f(v3); }
            if (resid) {
                const float* r0p = resid + (long)gm * ldc + gn;
                const float* r1p = resid + (long)(gm + 8) * ldc + gn;
                v0 += r0p[0]; v1 += r0p[1]; v2 += r1p[0]; v3 += r1p[1];
            }
            if (outHalf) {
                __half* C = (__half*)Cp;
                *(uint32_t*)(C + (long)gm * ldc + gn)       = h2pack(v0, v1);
                *(uint32_t*)(C + (long)(gm + 8) * ldc + gn) = h2pack(v2, v3);
            } else {
                float* C = (float*)Cp;
                *(float2*)(C + (long)gm * ldc + gn)       = make_float2(v0, v1);
                *(float2*)(C + (long)(gm + 8) * ldc + gn) = make_float2(v2, v3);
            }
        }
    }
}

// ---------------- dedicated logits kernel (M=2, fp32, memory-bound) ----------
__global__ __launch_bounds__(256)
void logits_k(const float* __restrict__ fin,
              const float* __restrict__ Wemb,
              float* __restrict__ out)
{
    __shared__ float f0[Dc], f1[Dc];
    int tid = threadIdx.x;
    for (int i = tid; i < Dc; i += 256) { f0[i] = fin[i]; f1[i] = fin[Dc + i]; }
    __syncthreads();
    int warp = tid >> 5, lane = tid & 31;
    long v = (long)blockIdx.x * 8 + warp;
    if (v >= Vc) return;
    const float* w = Wemb + v * Dc;
    float d0 = 0.f, d1 = 0.f;
    for (int i = lane * 4; i < Dc; i += 128) {
        float4 wv = *(const float4*)(w + i);
        d0 += wv.x * f0[i] + wv.y * f0[i+1] + wv.z * f0[i+2] + wv.w * f0[i+3];
        d1 += wv.x * f1[i] + wv.y * f1[i+1] + wv.z * f1[i+2] + wv.w * f1[i+3];
    }
#pragma unroll
    for (int o = 16; o > 0; o >>= 1) {
        d0 += __shfl_xor_sync(0xffffffff, d0, o);
        d1 += __shfl_xor_sync(0xffffffff, d1, o);
    }
    if (lane == 0) { out[v] = d0; out[(long)Vc + v] = d1; }
}

// ---------------- host-side launch helpers ----------------
static inline void launch_h(const __half* A, int lda, const __half* B, int ldb,
                            void* C, int ldc, int M, int N, int K,
                            const float* bias, const float* resid,
                            int gelu, int outHalf)
{
    dim3 g(N / BN, M / BM, 1);
    gemm_h<<<g, 256>>>(A, lda, B, ldb, C, ldc, K, bias, resid, gelu, outHalf);
}
static inline void launch_cvt(const float* s, __half* d, long n)
{
    long blocks = (n / 4 + 255) / 256;
    cvtk<<<(unsigned)blocks, 256>>>(s, d, n);
}
static inline void launch_cvt_s(const float* s, __half* d, long n,
                                long per, long strideDst, long off)
{
    long blocks = (n / 4 + 255) / 256;
    cvtk_s<<<(unsigned)blocks, 256>>>(s, d, n, per, strideDst, off);
}

extern "C" void kernel_launch(void* const* d_in, const int* in_sizes, int n_in,
                              void* d_out, int out_size)
{
    const int*   x    = (const int*)  d_in[0];
    const float* Wemb = (const float*)d_in[1];
    const float* pos  = (const float*)d_in[2];
    const float* Wq   = (const float*)d_in[3];
    const float* Wk   = (const float*)d_in[4];
    const float* Wv   = (const float*)d_in[5];
    const float* Wo   = (const float*)d_in[6];
    const float* bo   = (const float*)d_in[7];
    const float* n1s  = (const float*)d_in[8];
    const float* n1b  = (const float*)d_in[9];
    const float* n2s  = (const float*)d_in[10];
    const float* n2b  = (const float*)d_in[11];
    const float* W1   = (const float*)d_in[12];
    const float* b1   = (const float*)d_in[13];
    const float* W2   = (const float*)d_in[14];
    const float* b2   = (const float*)d_in[15];
    const float* fs   = (const float*)d_in[16];
    const float* fb   = (const float*)d_in[17];
    float* out = (float*)d_out;

    float  *h, *fin;
    __half *xnh, *qkvh, *ctxh, *ffh;
    __half *wqkv16, *wo16, *w116, *w216;
    cudaGetSymbolAddress((void**)&h,     g_h);
    cudaGetSymbolAddress((void**)&fin,   g_fin);
    cudaGetSymbolAddress((void**)&xnh,   g_xnh);
    cudaGetSymbolAddress((void**)&qkvh,  g_qkvh);
    cudaGetSymbolAddress((void**)&ctxh,  g_ctxh);
    cudaGetSymbolAddress((void**)&ffh,   g_ffh);
    cudaGetSymbolAddress((void**)&wqkv16,g_wqkv16);
    cudaGetSymbolAddress((void**)&wo16,  g_wo16);
    cudaGetSymbolAddress((void**)&w116,  g_w116);
    cudaGetSymbolAddress((void**)&w216,  g_w216);

    const long TD = (long)Tc * Dc;
    const long DD = (long)Dc * Dc;
    const long FD = (long)DFFc * Dc;
    const int  D3 = 3 * Dc;

    // weights -> fp16 (once per launch; graph-capturable)
    launch_cvt_s(Wq, wqkv16, (long)Lc * DD, DD, 3 * DD, 0);
    launch_cvt_s(Wk, wqkv16, (long)Lc * DD, DD, 3 * DD, DD);
    launch_cvt_s(Wv, wqkv16, (long)Lc * DD, DD, 3 * DD, 2 * DD);
    launch_cvt(Wo, wo16, (long)Lc * DD);
    launch_cvt(W1, w116, (long)Lc * FD);
    launch_cvt(W2, w216, (long)Lc * FD);

    {
        long n = (long)BTc * Dc;
        embed_k<<<(unsigned)((n + 255) / 256), 256>>>(x, Wemb, pos, h);
    }

    for (int l = 0; l < Lc; l++) {
        const float* bol = bo + (long)l * Dc;
        const float* b1l = b1 + (long)l * DFFc;
        const float* b2l = b2 + (long)l * Dc;

        // LN1 -> fp16
        ln_k<<<BTc, 256>>>(h, Dc, xnh, Dc, 1, n1s + (long)l * Dc, n1b + (long)l * Dc);

        // QKV = xn @ Wqkv^T  (fused, fp16 in/out, N=3072)
        launch_h(xnh, Dc, wqkv16 + (long)l * 3 * DD, Dc, qkvh, D3,
                 BTc, D3, Dc, 0, 0, 0, 1);

        // fused causal attention (fp16 I/O, QKV row stride 3*Dc)
        {
            dim3 fg(Tc / 128, Bc * Hc);
            flash_k<<<fg, 256>>>(qkvh, qkvh + Dc, qkvh + 2 * Dc, ctxh, D3);
        }

        // h = h + ctx @ Wo^T + bo  (fp32 out)
        launch_h(ctxh, Dc, wo16 + (long)l * DD, Dc, h, Dc, BTc, Dc, Dc, bol, h, 0, 0);

        // LN2 -> fp16
        ln_k<<<BTc, 256>>>(h, Dc, xnh, Dc, 1, n2s + (long)l * Dc, n2b + (long)l * Dc);

        // ff = gelu(xn @ W1^T + b1)  (fp16 out)
        launch_h(xnh, Dc, w116 + (long)l * FD, Dc, ffh, DFFc, BTc, DFFc, Dc, b1l, 0, 1, 1);

        // h = h + ff @ W2^T + b2  (fp32 out)
        launch_h(ffh, DFFc, w216 + (long)l * FD, DFFc, h, Dc, BTc, Dc, DFFc, b2l, h, 0, 0);
    }

    // final LN on the 2 last-token rows only -> fp32
    ln_k<<<Bc, 256>>>(h + (long)(Tc - 1) * Dc, TD, fin, Dc, 0, fs, fb);

    // logits (fp32, memory-bound dedicated kernel)
    logits_k<<<(Vc + 7) / 8, 256>>>(fin, Wemb, out);
}

// round 16
// speedup vs baseline: 1.4020x; 1.2431x over previous
#include <cuda_runtime.h>
#include <cuda_bf16.h>
#include <cuda_fp16.h>
#include <math.h>
#include <stdint.h>

// ---------------- problem constants ----------------
#define Bc   2
#define Tc   2048
#define Dc   1024
#define Hc   16
#define HDc  64
#define DFFc 4096
#define Lc   8
#define Vc   50257
#define BTc  (Bc*Tc)          // 4096
#define EPSc 1e-5f

// ---------------- static device scratch (no allocs allowed) ----------------
__device__ float  g_h  [BTc*Dc];
__device__ float  g_fin[Bc*Dc];
__device__ __half g_xnh [BTc*Dc];
__device__ __half g_qkvh[(long)BTc*3*Dc];
__device__ __half g_ctxh[BTc*Dc];
__device__ __half g_ffh [(long)BTc*DFFc];
// fp16 weights (converted once per launch)
__device__ __half g_wqkv16[(long)Lc*3*Dc*Dc];   // packed [L][3][Dc][Dc]
__device__ __half g_wo16[(long)Lc*Dc*Dc];
__device__ __half g_w116[(long)Lc*DFFc*Dc];
__device__ __half g_w216[(long)Lc*DFFc*Dc];

// ---------------- helpers ----------------
__device__ __forceinline__ float gelu_f(float x) {
    const float c = 0.7978845608028654f;
    return 0.5f * x * (1.0f + tanhf(c * (x + 0.044715f * x * x * x)));
}
__device__ __forceinline__ void mma_f16(float* c, const uint32_t* a, const uint32_t* b) {
    asm volatile(
        "mma.sync.aligned.m16n8k16.row.col.f32.f16.f16.f32 "
        "{%0,%1,%2,%3}, {%4,%5,%6,%7}, {%8,%9}, {%0,%1,%2,%3};"
        : "+f"(c[0]), "+f"(c[1]), "+f"(c[2]), "+f"(c[3])
        : "r"(a[0]), "r"(a[1]), "r"(a[2]), "r"(a[3]), "r"(b[0]), "r"(b[1]));
}
__device__ __forceinline__ uint32_t h2pack(float a, float b) {
    __half2 h = __floats2half2_rn(a, b);
    return *(uint32_t*)&h;
}
__device__ __forceinline__ uint32_t smem_u32(const void* p) {
    uint32_t a;
    asm("{ .reg .u64 t; cvta.to.shared.u64 t, %1; cvt.u32.u64 %0, t; }" : "=r"(a) : "l"(p));
    return a;
}
__device__ __forceinline__ void cpa16(uint32_t dst, const void* src) {
    asm volatile("cp.async.cg.shared.global [%0], [%1], 16;" :: "r"(dst), "l"(src));
}
#define CP_COMMIT() asm volatile("cp.async.commit_group;" ::: "memory")
#define CP_WAIT(n)  asm volatile("cp.async.wait_group %0;" :: "n"(n) : "memory")
__device__ __forceinline__ void ldsm4(uint32_t* r, uint32_t addr) {
    asm volatile("ldmatrix.sync.aligned.m8n8.x4.shared.b16 {%0,%1,%2,%3}, [%4];"
        : "=r"(r[0]), "=r"(r[1]), "=r"(r[2]), "=r"(r[3]) : "r"(addr));
}

// ---------------- fp32 -> fp16 conversions (weights, once per launch) -------
__global__ void cvtk(const float* __restrict__ s, __half* __restrict__ d, long n)
{
    long i = ((long)blockIdx.x * blockDim.x + threadIdx.x) * 4;
    if (i >= n) return;
    float4 v = *(const float4*)(s + i);
    uint2 o;
    o.x = h2pack(v.x, v.y);
    o.y = h2pack(v.z, v.w);
    *(uint2*)(d + i) = o;
}
__global__ void cvtk_s(const float* __restrict__ s, __half* __restrict__ d,
                       long n, long per, long strideDst, long off)
{
    long i = ((long)blockIdx.x * blockDim.x + threadIdx.x) * 4;
    if (i >= n) return;
    long l = i / per, r = i % per;
    float4 v = *(const float4*)(s + i);
    uint2 o;
    o.x = h2pack(v.x, v.y);
    o.y = h2pack(v.z, v.w);
    *(uint2*)(d + l * strideDst + off + r) = o;
}

// ---------------- embedding ----------------
__global__ void embed_k(const int* __restrict__ x,
                        const float* __restrict__ Wemb,
                        const float* __restrict__ pos,
                        float* __restrict__ h)
{
    long i = (long)blockIdx.x * blockDim.x + threadIdx.x;
    if (i >= (long)BTc * Dc) return;
    int row = (int)(i / Dc);
    int d   = (int)(i % Dc);
    int t   = row % Tc;
    int tok = x[row];
    h[i] = Wemb[(long)tok * Dc + d] + pos[(long)t * Dc + d];
}

// ---------------- layernorm (ddof=1, std+eps), fp16 or fp32 output ---------
__global__ void ln_k(const float* __restrict__ in, long inStride,
                     void* __restrict__ out, long outStride, int outHalf,
                     const float* __restrict__ sc, const float* __restrict__ sh)
{
    __shared__ float red[256];
    int r = blockIdx.x, tid = threadIdx.x;
    const float* x = in + (long)r * inStride;
    float xv[4];
    float s = 0.f;
#pragma unroll
    for (int i = 0; i < 4; i++) { xv[i] = x[tid + i * 256]; s += xv[i]; }
    red[tid] = s; __syncthreads();
    for (int st = 128; st > 0; st >>= 1) { if (tid < st) red[tid] += red[tid + st]; __syncthreads(); }
    float mean = red[0] * (1.0f / (float)Dc);
    __syncthreads();
    float v = 0.f;
#pragma unroll
    for (int i = 0; i < 4; i++) { float t = xv[i] - mean; v += t * t; }
    red[tid] = v; __syncthreads();
    for (int st = 128; st > 0; st >>= 1) { if (tid < st) red[tid] += red[tid + st]; __syncthreads(); }
    float inv = 1.0f / (sqrtf(red[0] / (float)(Dc - 1)) + EPSc);
#pragma unroll
    for (int i = 0; i < 4; i++) {
        int d = tid + i * 256;
        float o = sc[d] * ((xv[i] - mean) * inv) + sh[d];
        if (outHalf) ((__half*)out)[(long)r * outStride + d] = __float2half_rn(o);
        else         ((float*)out)[(long)r * outStride + d] = o;
    }
}

// =====================================================================
// flash_k (R12/R15-proven, fp16 I/O) with Q/K/V row-stride parameter ld.
// =====================================================================
__global__ __launch_bounds__(256)
void flash_k(const __half* __restrict__ Qg, const __half* __restrict__ Kg,
             const __half* __restrict__ Vg, __half* __restrict__ Og, int ld)
{
    __shared__ uint32_t usm[4608];           // 18432 B
    uint32_t* Qsh = usm;                     // [128][36]
    uint32_t* sKf = usm;                     // [4][8][64] = 8KB
    uint32_t* sVf = usm + 2048;              // [4][8][64] = 8KB

    int qt = (int)gridDim.x - 1 - blockIdx.x;
    int q0 = qt * 128;
    int z  = blockIdx.y;
    int b  = z / Hc, hh = z % Hc;
    long baseQ = (long)b * Tc * ld + (long)hh * HDc;
    const __half* Qb = Qg + baseQ;
    const __half* Kb = Kg + baseQ;
    const __half* Vb = Vg + baseQ;
    __half* Ob = Og + (long)b * Tc * Dc + (long)hh * HDc;

    int tid = threadIdx.x, lane = tid & 31, warp = tid >> 5;
    int g = lane >> 2, c = lane & 3;
    int physC = lane ^ ((lane >> 3) & 3);

    {
        int kr = tid >> 1, half = tid & 1;
        const uint4* src = (const uint4*)(Qb + (long)(q0 + kr) * ld + half * 32);
        uint32_t* dst = Qsh + kr * 36 + half * 16;
#pragma unroll
        for (int f = 0; f < 4; f++)
            *(uint4*)(dst + f * 4) = src[f];
    }
    __syncthreads();

    uint32_t qf[4][4];
    {
        int r0w = warp * 16 + g;
#pragma unroll
        for (int kb = 0; kb < 4; kb++) {
            int w = kb * 8 + c;
            qf[kb][0] = Qsh[r0w * 36 + w];
            qf[kb][1] = Qsh[(r0w + 8) * 36 + w];
            qf[kb][2] = Qsh[r0w * 36 + w + 4];
            qf[kb][3] = Qsh[(r0w + 8) * 36 + w + 4];
        }
    }
    __syncthreads();

    float oacc[8][4];
#pragma unroll
    for (int i = 0; i < 8; i++)
#pragma unroll
        for (int e = 0; e < 4; e++) oacc[i][e] = 0.f;
    float m0 = -1e30f, m1 = -1e30f, l0 = 0.f, l1 = 0.f;

    bool isK = tid < 128;
    int t = isK ? tid : (tid - 128);
    int nK  = t & 63;
    int kqK = t >> 6;
    int nbK = nK >> 3, gK = nK & 7;
    int swzK = (gK >> 1) & 3;
    int nbxK = (nbK & 1) << 3;
    const __half* KpBase = Kb + (long)nK * ld + kqK * 32;
    int kV = t & 63;
    int chV = t >> 6;
    int kbV = kV >> 4, kkV = kV & 15;
    int cV  = (kkV & 7) >> 1, hfV = (kkV >> 3) & 1, loV = kkV & 1;
    const __half* VpBase = Vb + (long)kV * ld + chV * 32;

    int nkt = 2 * qt + 2;
    for (int kt = 0; kt < nkt; kt++) {
        long koff = (long)(kt * 64) * ld;

        if (isK) {
#pragma unroll
            for (int i = 0; i < 2; i++) {
                int kb = 2 * kqK + i;
                const uint4* ps = (const uint4*)(KpBase + koff + i * 16);
                uint4 u0 = ps[0], u1 = ps[1];
                const uint32_t* W0 = (const uint32_t*)&u0;
                const uint32_t* W1 = (const uint32_t*)&u1;
                uint32_t* dst = sKf + kb * 512 + nbK * 64;
#pragma unroll
                for (int cc = 0; cc < 4; cc++) {
                    int s = ((4 * gK + cc) ^ swzK) ^ nbxK;
                    dst[s * 2 + 0] = W0[cc];
                    dst[s * 2 + 1] = W1[cc];
                }
            }
        } else {
            const uint4* vp = (const uint4*)(VpBase + koff);
            uint32_t* dstK = sVf + kbV * 512;
#pragma unroll
            for (int u = 0; u < 4; u++) {
                uint4 vv = vp[u];
                const uint32_t* W = (const uint32_t*)&vv;
#pragma unroll
                for (int w = 0; w < 4; w++) {
                    __half2 h2 = *(__half2*)&W[w];
#pragma unroll
                    for (int hw = 0; hw < 2; hw++) {
                        int j = u * 8 + w * 2 + hw;
                        int n = chV * 32 + j;
                        int nb = n >> 3, gg = n & 7;
                        int s = ((4 * gg + cV) ^ ((gg >> 1) & 3)) ^ ((nb & 1) << 3);
                        __half* hp = (__half*)&dstK[nb * 64 + s * 2 + hfV];
                        hp[loV] = hw ? __high2half(h2) : __low2half(h2);
                    }
                }
            }
        }
        __syncthreads();

        int k0 = kt * 64;
        bool active = (k0 <= q0 + warp * 16 + 15);
        if (active) {
            float sacc[8][4];
#pragma unroll
            for (int i = 0; i < 8; i++)
#pragma unroll
                for (int e = 0; e < 4; e++) sacc[i][e] = 0.f;
#pragma unroll
            for (int kb = 0; kb < 4; kb++) {
#pragma unroll
                for (int nb = 0; nb < 8; nb++) {
                    uint2 bk = *(uint2*)&sKf[kb * 512 + nb * 64 +
                                             (physC ^ ((nb & 1) << 3)) * 2];
                    mma_f16(sacc[nb], qf[kb], &bk.x);
                }
            }

            int qr0 = q0 + warp * 16 + g;
            int qr1 = qr0 + 8;
            bool maskNeed = (k0 + 63 > q0 + warp * 16);
            float rm0 = -1e30f, rm1 = -1e30f;
#pragma unroll
            for (int ni = 0; ni < 8; ni++) {
#pragma unroll
                for (int e = 0; e < 4; e++) {
                    float vvv = sacc[ni][e] * 0.125f;
                    if (maskNeed) {
                        int kc = k0 + ni * 8 + c * 2 + (e & 1);
                        if (kc > ((e >= 2) ? qr1 : qr0)) vvv = -1e30f;
                    }
                    sacc[ni][e] = vvv;
                    if (e < 2) rm0 = fmaxf(rm0, vvv); else rm1 = fmaxf(rm1, vvv);
                }
            }
            rm0 = fmaxf(rm0, __shfl_xor_sync(0xffffffffu, rm0, 1));
            rm0 = fmaxf(rm0, __shfl_xor_sync(0xffffffffu, rm0, 2));
            rm1 = fmaxf(rm1, __shfl_xor_sync(0xffffffffu, rm1, 1));
            rm1 = fmaxf(rm1, __shfl_xor_sync(0xffffffffu, rm1, 2));
            float mn0 = fmaxf(m0, rm0), mn1 = fmaxf(m1, rm1);
            float sc0 = __expf(m0 - mn0), sc1 = __expf(m1 - mn1);
            float rs0 = 0.f, rs1 = 0.f;
#pragma unroll
            for (int ni = 0; ni < 8; ni++) {
#pragma unroll
                for (int e = 0; e < 4; e++) {
                    float ee = __expf(sacc[ni][e] - ((e < 2) ? mn0 : mn1));
                    sacc[ni][e] = ee;
                    if (e < 2) rs0 += ee; else rs1 += ee;
                }
            }
            rs0 += __shfl_xor_sync(0xffffffffu, rs0, 1);
            rs0 += __shfl_xor_sync(0xffffffffu, rs0, 2);
            rs1 += __shfl_xor_sync(0xffffffffu, rs1, 1);
            rs1 += __shfl_xor_sync(0xffffffffu, rs1, 2);
            l0 = l0 * sc0 + rs0;
            l1 = l1 * sc1 + rs1;
            m0 = mn0; m1 = mn1;
#pragma unroll
            for (int ni = 0; ni < 8; ni++) {
#pragma unroll
                for (int e = 0; e < 4; e++) oacc[ni][e] *= (e < 2) ? sc0 : sc1;
            }

#pragma unroll
            for (int kb = 0; kb < 4; kb++) {
                uint32_t pf[4];
                pf[0] = h2pack(sacc[2 * kb][0],     sacc[2 * kb][1]);
                pf[1] = h2pack(sacc[2 * kb][2],     sacc[2 * kb][3]);
                pf[2] = h2pack(sacc[2 * kb + 1][0], sacc[2 * kb + 1][1]);
                pf[3] = h2pack(sacc[2 * kb + 1][2], sacc[2 * kb + 1][3]);
#pragma unroll
                for (int nb = 0; nb < 8; nb++) {
                    uint2 bv = *(uint2*)&sVf[kb * 512 + nb * 64 +
                                             (physC ^ ((nb & 1) << 3)) * 2];
                    mma_f16(oacc[nb], pf, &bv.x);
                }
            }
        }
        __syncthreads();
    }

    float il0 = 1.f / l0, il1 = 1.f / l1;
    int r0 = q0 + warp * 16 + g;
#pragma unroll
    for (int ni = 0; ni < 8; ni++) {
        int d = ni * 8 + 2 * c;
        *(uint32_t*)(Ob + (long)r0 * Dc + d) =
            h2pack(oacc[ni][0] * il0, oacc[ni][1] * il0);
        *(uint32_t*)(Ob + (long)(r0 + 8) * Dc + d) =
            h2pack(oacc[ni][2] * il1, oacc[ni][3] * il1);
    }
}

// =====================================================================
// gemm_h v2: cp.async + ldmatrix multistage NT GEMM, fp16 ops, fp32 accum.
// 128x128 block, 8 warps of 64x32 tiles, BK=16, 3 stages, 2 CTA/SM.
// smem/stage: A 4KB (128 rows x 32B) + B 4KB; swizzle (s ^ ((r>>2)&1)).
// C = A[M,K] @ B[N,K]^T [+bias][gelu][+resid]; out fp16 or fp32.
// =====================================================================
#define BM 128
#define BN 128
#define NST 3

__global__ __launch_bounds__(256, 2)
void gemm_h(const __half* __restrict__ A, int lda,
            const __half* __restrict__ B, int ldb,
            void* __restrict__ Cp, int ldc, int K,
            const float* __restrict__ bias,
            const float* __restrict__ resid, int doGelu, int outHalf)
{
    __shared__ __align__(16) char smem[NST * 8192];
    uint32_t sb = smem_u32(smem);

    int m0 = blockIdx.y * BM, n0 = blockIdx.x * BN;
    int tid = threadIdx.x, lane = tid & 31, warp = tid >> 5;
    int wm = (warp & 1) * 64, wn = (warp >> 1) * 32;
    int nb0 = wn >> 3;

    float acc[4][4][4];
#pragma unroll
    for (int i = 0; i < 4; i++)
#pragma unroll
        for (int jx = 0; jx < 4; jx++)
#pragma unroll
            for (int e = 0; e < 4; e++) acc[i][jx][e] = 0.f;

    // ---- staging role: thread -> (row, 16B segment) for A and B tiles ----
    int r  = tid >> 1, sg = tid & 1;
    const __half* Ap = A + (long)(m0 + r) * lda + sg * 8;
    const __half* Bp = B + (long)(n0 + r) * ldb + sg * 8;
    uint32_t soff = (uint32_t)(r * 32 + ((sg ^ ((r >> 2) & 1)) << 4));

    // ---- consumer ldmatrix addresses ----
    uint32_t offA[4], offB[2];
#pragma unroll
    for (int mi = 0; mi < 4; mi++) {
        int rA = wm + mi * 16 + (lane & 15);
        int sA = lane >> 4;
        offA[mi] = (uint32_t)(rA * 32 + ((sA ^ ((rA >> 2) & 1)) << 4));
    }
#pragma unroll
    for (int p = 0; p < 2; p++) {
        int rB = (nb0 + 2 * p + ((lane >> 4) & 1)) * 8 + (lane & 7);
        int sB = (lane >> 3) & 1;
        offB[p] = (uint32_t)(4096 + rB * 32 + ((sB ^ ((rB >> 2) & 1)) << 4));
    }

    int nIter = K / 16;

    // ---- prologue: stages 0, 1 ----
    cpa16(sb + soff,        Ap);
    cpa16(sb + 4096 + soff, Bp);
    CP_COMMIT();
    cpa16(sb + 8192 + soff,        Ap + 16);
    cpa16(sb + 8192 + 4096 + soff, Bp + 16);
    CP_COMMIT();

    int stg = 0;
    for (int it = 0; it < nIter; it++) {
        if (it + 1 < nIter) { CP_WAIT(1); } else { CP_WAIT(0); }
        __syncthreads();
        if (it + 2 < nIter) {
            int s2 = (it + 2) % NST;
            long ko = (long)(it + 2) * 16;
            cpa16(sb + s2 * 8192 + soff,        Ap + ko);
            cpa16(sb + s2 * 8192 + 4096 + soff, Bp + ko);
            CP_COMMIT();
        }

        uint32_t base = sb + stg * 8192;
        uint32_t af[4][4], bf[2][4];
#pragma unroll
        for (int mi = 0; mi < 4; mi++) ldsm4(af[mi], base + offA[mi]);
#pragma unroll
        for (int p = 0; p < 2; p++)    ldsm4(bf[p], base + offB[p]);
#pragma unroll
        for (int mi = 0; mi < 4; mi++) {
            mma_f16(acc[mi][0], af[mi], &bf[0][0]);
            mma_f16(acc[mi][1], af[mi], &bf[0][2]);
            mma_f16(acc[mi][2], af[mi], &bf[1][0]);
            mma_f16(acc[mi][3], af[mi], &bf[1][2]);
        }
        stg = (stg + 1 == NST) ? 0 : stg + 1;
    }

    // ---- epilogue (identical to R12) ----
    int ge = lane >> 2, c2 = (lane & 3) * 2;
#pragma unroll
    for (int mi = 0; mi < 4; mi++) {
#pragma unroll
        for (int ni = 0; ni < 4; ni++) {
            int gm = m0 + wm + mi * 16 + ge;
            int gn = n0 + wn + ni * 8 + c2;
            float v0 = acc[mi][ni][0], v1 = acc[mi][ni][1];
            float v2 = acc[mi][ni][2], v3 = acc[mi][ni][3];
            if (bias) {
                float b0 = bias[gn], b1 = bias[gn + 1];
                v0 += b0; v1 += b1; v2 += b0; v3 += b1;
            }
            if (doGelu) { v0 = gelu_f(v0); v1 = gelu_f(v1); v2 = gelu_f(v2); v3 = gelu_f(v3); }
            if (resid) {
                const float* r0p = resid + (long)gm * ldc + gn;
                const float* r1p = resid + (long)(gm + 8) * ldc + gn;
                v0 += r0p[0]; v1 += r0p[1]; v2 += r1p[0]; v3 += r1p[1];
            }
            if (outHalf) {
                __half* C = (__half*)Cp;
                *(uint32_t*)(C + (long)gm * ldc + gn)       = h2pack(v0, v1);
                *(uint32_t*)(C + (long)(gm + 8) * ldc + gn) = h2pack(v2, v3);
            } else {
                float* C = (float*)Cp;
                *(float2*)(C + (long)gm * ldc + gn)       = make_float2(v0, v1);
                *(float2*)(C + (long)(gm + 8) * ldc + gn) = make_float2(v2, v3);
            }
        }
    }
}

// ---------------- dedicated logits kernel (M=2, fp32, memory-bound) ----------
__global__ __launch_bounds__(256)
void logits_k(const float* __restrict__ fin,
              const float* __restrict__ Wemb,
              float* __restrict__ out)
{
    __shared__ float f0[Dc], f1[Dc];
    int tid = threadIdx.x;
    for (int i = tid; i < Dc; i += 256) { f0[i] = fin[i]; f1[i] = fin[Dc + i]; }
    __syncthreads();
    int warp = tid >> 5, lane = tid & 31;
    long v = (long)blockIdx.x * 8 + warp;
    if (v >= Vc) return;
    const float* w = Wemb + v * Dc;
    float d0 = 0.f, d1 = 0.f;
    for (int i = lane * 4; i < Dc; i += 128) {
        float4 wv = *(const float4*)(w + i);
        d0 += wv.x * f0[i] + wv.y * f0[i+1] + wv.z * f0[i+2] + wv.w * f0[i+3];
        d1 += wv.x * f1[i] + wv.y * f1[i+1] + wv.z * f1[i+2] + wv.w * f1[i+3];
    }
#pragma unroll
    for (int o = 16; o > 0; o >>= 1) {
        d0 += __shfl_xor_sync(0xffffffff, d0, o);
        d1 += __shfl_xor_sync(0xffffffff, d1, o);
    }
    if (lane == 0) { out[v] = d0; out[(long)Vc + v] = d1; }
}

// ---------------- host-side launch helpers ----------------
static inline void launch_h(const __half* A, int lda, const __half* B, int ldb,
                            void* C, int ldc, int M, int N, int K,
                            const float* bias, const float* resid,
                            int gelu, int outHalf)
{
    dim3 g(N / BN, M / BM, 1);
    gemm_h<<<g, 256>>>(A, lda, B, ldb, C, ldc, K, bias, resid, gelu, outHalf);
}
static inline void launch_cvt(const float* s, __half* d, long n)
{
    long blocks = (n / 4 + 255) / 256;
    cvtk<<<(unsigned)blocks, 256>>>(s, d, n);
}
static inline void launch_cvt_s(const float* s, __half* d, long n,
                                long per, long strideDst, long off)
{
    long blocks = (n / 4 + 255) / 256;
    cvtk_s<<<(unsigned)blocks, 256>>>(s, d, n, per, strideDst, off);
}

extern "C" void kernel_launch(void* const* d_in, const int* in_sizes, int n_in,
                              void* d_out, int out_size)
{
    const int*   x    = (const int*)  d_in[0];
    const float* Wemb = (const float*)d_in[1];
    const float* pos  = (const float*)d_in[2];
    const float* Wq   = (const float*)d_in[3];
    const float* Wk   = (const float*)d_in[4];
    const float* Wv   = (const float*)d_in[5];
    const float* Wo   = (const float*)d_in[6];
    const float* bo   = (const float*)d_in[7];
    const float* n1s  = (const float*)d_in[8];
    const float* n1b  = (const float*)d_in[9];
    const float* n2s  = (const float*)d_in[10];
    const float* n2b  = (const float*)d_in[11];
    const float* W1   = (const float*)d_in[12];
    const float* b1   = (const float*)d_in[13];
    const float* W2   = (const float*)d_in[14];
    const float* b2   = (const float*)d_in[15];
    const float* fs   = (const float*)d_in[16];
    const float* fb   = (const float*)d_in[17];
    float* out = (float*)d_out;

    float  *h, *fin;
    __half *xnh, *qkvh, *ctxh, *ffh;
    __half *wqkv16, *wo16, *w116, *w216;
    cudaGetSymbolAddress((void**)&h,     g_h);
    cudaGetSymbolAddress((void**)&fin,   g_fin);
    cudaGetSymbolAddress((void**)&xnh,   g_xnh);
    cudaGetSymbolAddress((void**)&qkvh,  g_qkvh);
    cudaGetSymbolAddress((void**)&ctxh,  g_ctxh);
    cudaGetSymbolAddress((void**)&ffh,   g_ffh);
    cudaGetSymbolAddress((void**)&wqkv16,g_wqkv16);
    cudaGetSymbolAddress((void**)&wo16,  g_wo16);
    cudaGetSymbolAddress((void**)&w116,  g_w116);
    cudaGetSymbolAddress((void**)&w216,  g_w216);

    const long TD = (long)Tc * Dc;
    const long DD = (long)Dc * Dc;
    const long FD = (long)DFFc * Dc;
    const int  D3 = 3 * Dc;

    // weights -> fp16 (once per launch; graph-capturable)
    launch_cvt_s(Wq, wqkv16, (long)Lc * DD, DD, 3 * DD, 0);
    launch_cvt_s(Wk, wqkv16, (long)Lc * DD, DD, 3 * DD, DD);
    launch_cvt_s(Wv, wqkv16, (long)Lc * DD, DD, 3 * DD, 2 * DD);
    launch_cvt(Wo, wo16, (long)Lc * DD);
    launch_cvt(W1, w116, (long)Lc * FD);
    launch_cvt(W2, w216, (long)Lc * FD);

    {
        long n = (long)BTc * Dc;
        embed_k<<<(unsigned)((n + 255) / 256), 256>>>(x, Wemb, pos, h);
    }

    for (int l = 0; l < Lc; l++) {
        const float* bol = bo + (long)l * Dc;
        const float* b1l = b1 + (long)l * DFFc;
        const float* b2l = b2 + (long)l * Dc;

        // LN1 -> fp16
        ln_k<<<BTc, 256>>>(h, Dc, xnh, Dc, 1, n1s + (long)l * Dc, n1b + (long)l * Dc);

        // QKV = xn @ Wqkv^T  (fused, fp16 in/out, N=3072)
        launch_h(xnh, Dc, wqkv16 + (long)l * 3 * DD, Dc, qkvh, D3,
                 BTc, D3, Dc, 0, 0, 0, 1);

        // fused causal attention (fp16 I/O, QKV row stride 3*Dc)
        {
            dim3 fg(Tc / 128, Bc * Hc);
            flash_k<<<fg, 256>>>(qkvh, qkvh + Dc, qkvh + 2 * Dc, ctxh, D3);
        }

        // h = h + ctx @ Wo^T + bo  (fp32 out)
        launch_h(ctxh, Dc, wo16 + (long)l * DD, Dc, h, Dc, BTc, Dc, Dc, bol, h, 0, 0);

        // LN2 -> fp16
        ln_k<<<BTc, 256>>>(h, Dc, xnh, Dc, 1, n2s + (long)l * Dc, n2b + (long)l * Dc);

        // ff = gelu(xn @ W1^T + b1)  (fp16 out)
        launch_h(xnh, Dc, w116 + (long)l * FD, Dc, ffh, DFFc, BTc, DFFc, Dc, b1l, 0, 1, 1);

        // h = h + ff @ W2^T + b2  (fp32 out)
        launch_h(ffh, DFFc, w216 + (long)l * FD, DFFc, h, Dc, BTc, Dc, DFFc, b2l, h, 0, 0);
    }

    // final LN on the 2 last-token rows only -> fp32
    ln_k<<<Bc, 256>>>(h + (long)(Tc - 1) * Dc, TD, fin, Dc, 0, fs, fb);

    // logits (fp32, memory-bound dedicated kernel)
    logits_k<<<(Vc + 7) / 8, 256>>>(fin, Wemb, out);
}

// round 17
// speedup vs baseline: 1.5269x; 1.0891x over previous
#include <cuda_runtime.h>
#include <cuda_bf16.h>
#include <cuda_fp16.h>
#include <math.h>
#include <stdint.h>

// ---------------- problem constants ----------------
#define Bc   2
#define Tc   2048
#define Dc   1024
#define Hc   16
#define HDc  64
#define DFFc 4096
#define Lc   8
#define Vc   50257
#define BTc  (Bc*Tc)          // 4096
#define EPSc 1e-5f

// ---------------- static device scratch (no allocs allowed) ----------------
__device__ float  g_h  [BTc*Dc];
__device__ float  g_fin[Bc*Dc];
__device__ __half g_xnh [BTc*Dc];
__device__ __half g_qkvh[(long)BTc*3*Dc];
__device__ __half g_ctxh[BTc*Dc];
__device__ __half g_ffh [(long)BTc*DFFc];
// fp16 weights (converted once per launch)
__device__ __half g_wqkv16[(long)Lc*3*Dc*Dc];   // packed [L][3][Dc][Dc]
__device__ __half g_wo16[(long)Lc*Dc*Dc];
__device__ __half g_w116[(long)Lc*DFFc*Dc];
__device__ __half g_w216[(long)Lc*DFFc*Dc];

// ---------------- helpers ----------------
__device__ __forceinline__ float gelu_f(float x) {
    const float c = 0.7978845608028654f;
    return 0.5f * x * (1.0f + tanhf(c * (x + 0.044715f * x * x * x)));
}
__device__ __forceinline__ void mma_f16(float* c, const uint32_t* a, const uint32_t* b) {
    asm volatile(
        "mma.sync.aligned.m16n8k16.row.col.f32.f16.f16.f32 "
        "{%0,%1,%2,%3}, {%4,%5,%6,%7}, {%8,%9}, {%0,%1,%2,%3};"
        : "+f"(c[0]), "+f"(c[1]), "+f"(c[2]), "+f"(c[3])
        : "r"(a[0]), "r"(a[1]), "r"(a[2]), "r"(a[3]), "r"(b[0]), "r"(b[1]));
}
__device__ __forceinline__ uint32_t h2pack(float a, float b) {
    __half2 h = __floats2half2_rn(a, b);
    return *(uint32_t*)&h;
}
__device__ __forceinline__ uint32_t smem_u32(const void* p) {
    uint32_t a;
    asm("{ .reg .u64 t; cvta.to.shared.u64 t, %1; cvt.u32.u64 %0, t; }" : "=r"(a) : "l"(p));
    return a;
}
__device__ __forceinline__ void cpa16(uint32_t dst, const void* src) {
    asm volatile("cp.async.cg.shared.global [%0], [%1], 16;" :: "r"(dst), "l"(src));
}
#define CP_COMMIT() asm volatile("cp.async.commit_group;" ::: "memory")
#define CP_WAIT(n)  asm volatile("cp.async.wait_group %0;" :: "n"(n) : "memory")
__device__ __forceinline__ void ldsm4(uint32_t* r, uint32_t addr) {
    asm volatile("ldmatrix.sync.aligned.m8n8.x4.shared.b16 {%0,%1,%2,%3}, [%4];"
        : "=r"(r[0]), "=r"(r[1]), "=r"(r[2]), "=r"(r[3]) : "r"(addr));
}

// ---------------- fp32 -> fp16 conversions (weights, once per launch) -------
__global__ void cvtk(const float* __restrict__ s, __half* __restrict__ d, long n)
{
    long i = ((long)blockIdx.x * blockDim.x + threadIdx.x) * 4;
    if (i >= n) return;
    float4 v = *(const float4*)(s + i);
    uint2 o;
    o.x = h2pack(v.x, v.y);
    o.y = h2pack(v.z, v.w);
    *(uint2*)(d + i) = o;
}
__global__ void cvtk_s(const float* __restrict__ s, __half* __restrict__ d,
                       long n, long per, long strideDst, long off)
{
    long i = ((long)blockIdx.x * blockDim.x + threadIdx.x) * 4;
    if (i >= n) return;
    long l = i / per, r = i % per;
    float4 v = *(const float4*)(s + i);
    uint2 o;
    o.x = h2pack(v.x, v.y);
    o.y = h2pack(v.z, v.w);
    *(uint2*)(d + l * strideDst + off + r) = o;
}

// ---------------- embedding ----------------
__global__ void embed_k(const int* __restrict__ x,
                        const float* __restrict__ Wemb,
                        const float* __restrict__ pos,
                        float* __restrict__ h)
{
    long i = (long)blockIdx.x * blockDim.x + threadIdx.x;
    if (i >= (long)BTc * Dc) return;
    int row = (int)(i / Dc);
    int d   = (int)(i % Dc);
    int t   = row % Tc;
    int tok = x[row];
    h[i] = Wemb[(long)tok * Dc + d] + pos[(long)t * Dc + d];
}

// ---------------- layernorm (ddof=1, std+eps), fp16 or fp32 output ---------
__global__ void ln_k(const float* __restrict__ in, long inStride,
                     void* __restrict__ out, long outStride, int outHalf,
                     const float* __restrict__ sc, const float* __restrict__ sh)
{
    __shared__ float red[256];
    int r = blockIdx.x, tid = threadIdx.x;
    const float* x = in + (long)r * inStride;
    float xv[4];
    float s = 0.f;
#pragma unroll
    for (int i = 0; i < 4; i++) { xv[i] = x[tid + i * 256]; s += xv[i]; }
    red[tid] = s; __syncthreads();
    for (int st = 128; st > 0; st >>= 1) { if (tid < st) red[tid] += red[tid + st]; __syncthreads(); }
    float mean = red[0] * (1.0f / (float)Dc);
    __syncthreads();
    float v = 0.f;
#pragma unroll
    for (int i = 0; i < 4; i++) { float t = xv[i] - mean; v += t * t; }
    red[tid] = v; __syncthreads();
    for (int st = 128; st > 0; st >>= 1) { if (tid < st) red[tid] += red[tid + st]; __syncthreads(); }
    float inv = 1.0f / (sqrtf(red[0] / (float)(Dc - 1)) + EPSc);
#pragma unroll
    for (int i = 0; i < 4; i++) {
        int d = tid + i * 256;
        float o = sc[d] * ((xv[i] - mean) * inv) + sh[d];
        if (outHalf) ((__half*)out)[(long)r * outStride + d] = __float2half_rn(o);
        else         ((float*)out)[(long)r * outStride + d] = o;
    }
}

// =====================================================================
// flash_k (R12/R15-proven, fp16 I/O) with Q/K/V row-stride parameter ld.
// =====================================================================
__global__ __launch_bounds__(256)
void flash_k(const __half* __restrict__ Qg, const __half* __restrict__ Kg,
             const __half* __restrict__ Vg, __half* __restrict__ Og, int ld)
{
    __shared__ uint32_t usm[4608];           // 18432 B
    uint32_t* Qsh = usm;                     // [128][36]
    uint32_t* sKf = usm;                     // [4][8][64] = 8KB
    uint32_t* sVf = usm + 2048;              // [4][8][64] = 8KB

    int qt = (int)gridDim.x - 1 - blockIdx.x;
    int q0 = qt * 128;
    int z  = blockIdx.y;
    int b  = z / Hc, hh = z % Hc;
    long baseQ = (long)b * Tc * ld + (long)hh * HDc;
    const __half* Qb = Qg + baseQ;
    const __half* Kb = Kg + baseQ;
    const __half* Vb = Vg + baseQ;
    __half* Ob = Og + (long)b * Tc * Dc + (long)hh * HDc;

    int tid = threadIdx.x, lane = tid & 31, warp = tid >> 5;
    int g = lane >> 2, c = lane & 3;
    int physC = lane ^ ((lane >> 3) & 3);

    {
        int kr = tid >> 1, half = tid & 1;
        const uint4* src = (const uint4*)(Qb + (long)(q0 + kr) * ld + half * 32);
        uint32_t* dst = Qsh + kr * 36 + half * 16;
#pragma unroll
        for (int f = 0; f < 4; f++)
            *(uint4*)(dst + f * 4) = src[f];
    }
    __syncthreads();

    uint32_t qf[4][4];
    {
        int r0w = warp * 16 + g;
#pragma unroll
        for (int kb = 0; kb < 4; kb++) {
            int w = kb * 8 + c;
            qf[kb][0] = Qsh[r0w * 36 + w];
            qf[kb][1] = Qsh[(r0w + 8) * 36 + w];
            qf[kb][2] = Qsh[r0w * 36 + w + 4];
            qf[kb][3] = Qsh[(r0w + 8) * 36 + w + 4];
        }
    }
    __syncthreads();

    float oacc[8][4];
#pragma unroll
    for (int i = 0; i < 8; i++)
#pragma unroll
        for (int e = 0; e < 4; e++) oacc[i][e] = 0.f;
    float m0 = -1e30f, m1 = -1e30f, l0 = 0.f, l1 = 0.f;

    bool isK = tid < 128;
    int t = isK ? tid : (tid - 128);
    int nK  = t & 63;
    int kqK = t >> 6;
    int nbK = nK >> 3, gK = nK & 7;
    int swzK = (gK >> 1) & 3;
    int nbxK = (nbK & 1) << 3;
    const __half* KpBase = Kb + (long)nK * ld + kqK * 32;
    int kV = t & 63;
    int chV = t >> 6;
    int kbV = kV >> 4, kkV = kV & 15;
    int cV  = (kkV & 7) >> 1, hfV = (kkV >> 3) & 1, loV = kkV & 1;
    const __half* VpBase = Vb + (long)kV * ld + chV * 32;

    int nkt = 2 * qt + 2;
    for (int kt = 0; kt < nkt; kt++) {
        long koff = (long)(kt * 64) * ld;

        if (isK) {
#pragma unroll
            for (int i = 0; i < 2; i++) {
                int kb = 2 * kqK + i;
                const uint4* ps = (const uint4*)(KpBase + koff + i * 16);
                uint4 u0 = ps[0], u1 = ps[1];
                const uint32_t* W0 = (const uint32_t*)&u0;
                const uint32_t* W1 = (const uint32_t*)&u1;
                uint32_t* dst = sKf + kb * 512 + nbK * 64;
#pragma unroll
                for (int cc = 0; cc < 4; cc++) {
                    int s = ((4 * gK + cc) ^ swzK) ^ nbxK;
                    dst[s * 2 + 0] = W0[cc];
                    dst[s * 2 + 1] = W1[cc];
                }
            }
        } else {
            const uint4* vp = (const uint4*)(VpBase + koff);
            uint32_t* dstK = sVf + kbV * 512;
#pragma unroll
            for (int u = 0; u < 4; u++) {
                uint4 vv = vp[u];
                const uint32_t* W = (const uint32_t*)&vv;
#pragma unroll
                for (int w = 0; w < 4; w++) {
                    __half2 h2 = *(__half2*)&W[w];
#pragma unroll
                    for (int hw = 0; hw < 2; hw++) {
                        int j = u * 8 + w * 2 + hw;
                        int n = chV * 32 + j;
                        int nb = n >> 3, gg = n & 7;
                        int s = ((4 * gg + cV) ^ ((gg >> 1) & 3)) ^ ((nb & 1) << 3);
                        __half* hp = (__half*)&dstK[nb * 64 + s * 2 + hfV];
                        hp[loV] = hw ? __high2half(h2) : __low2half(h2);
                    }
                }
            }
        }
        __syncthreads();

        int k0 = kt * 64;
        bool active = (k0 <= q0 + warp * 16 + 15);
        if (active) {
            float sacc[8][4];
#pragma unroll
            for (int i = 0; i < 8; i++)
#pragma unroll
                for (int e = 0; e < 4; e++) sacc[i][e] = 0.f;
#pragma unroll
            for (int kb = 0; kb < 4; kb++) {
#pragma unroll
                for (int nb = 0; nb < 8; nb++) {
                    uint2 bk = *(uint2*)&sKf[kb * 512 + nb * 64 +
                                             (physC ^ ((nb & 1) << 3)) * 2];
                    mma_f16(sacc[nb], qf[kb], &bk.x);
                }
            }

            int qr0 = q0 + warp * 16 + g;
            int qr1 = qr0 + 8;
            bool maskNeed = (k0 + 63 > q0 + warp * 16);
            float rm0 = -1e30f, rm1 = -1e30f;
#pragma unroll
            for (int ni = 0; ni < 8; ni++) {
#pragma unroll
                for (int e = 0; e < 4; e++) {
                    float vvv = sacc[ni][e] * 0.125f;
                    if (maskNeed) {
                        int kc = k0 + ni * 8 + c * 2 + (e & 1);
                        if (kc > ((e >= 2) ? qr1 : qr0)) vvv = -1e30f;
                    }
                    sacc[ni][e] = vvv;
                    if (e < 2) rm0 = fmaxf(rm0, vvv); else rm1 = fmaxf(rm1, vvv);
                }
            }
            rm0 = fmaxf(rm0, __shfl_xor_sync(0xffffffffu, rm0, 1));
            rm0 = fmaxf(rm0, __shfl_xor_sync(0xffffffffu, rm0, 2));
            rm1 = fmaxf(rm1, __shfl_xor_sync(0xffffffffu, rm1, 1));
            rm1 = fmaxf(rm1, __shfl_xor_sync(0xffffffffu, rm1, 2));
            float mn0 = fmaxf(m0, rm0), mn1 = fmaxf(m1, rm1);
            float sc0 = __expf(m0 - mn0), sc1 = __expf(m1 - mn1);
            float rs0 = 0.f, rs1 = 0.f;
#pragma unroll
            for (int ni = 0; ni < 8; ni++) {
#pragma unroll
                for (int e = 0; e < 4; e++) {
                    float ee = __expf(sacc[ni][e] - ((e < 2) ? mn0 : mn1));
                    sacc[ni][e] = ee;
                    if (e < 2) rs0 += ee; else rs1 += ee;
                }
            }
            rs0 += __shfl_xor_sync(0xffffffffu, rs0, 1);
            rs0 += __shfl_xor_sync(0xffffffffu, rs0, 2);
            rs1 += __shfl_xor_sync(0xffffffffu, rs1, 1);
            rs1 += __shfl_xor_sync(0xffffffffu, rs1, 2);
            l0 = l0 * sc0 + rs0;
            l1 = l1 * sc1 + rs1;
            m0 = mn0; m1 = mn1;
#pragma unroll
            for (int ni = 0; ni < 8; ni++) {
#pragma unroll
                for (int e = 0; e < 4; e++) oacc[ni][e] *= (e < 2) ? sc0 : sc1;
            }

#pragma unroll
            for (int kb = 0; kb < 4; kb++) {
                uint32_t pf[4];
                pf[0] = h2pack(sacc[2 * kb][0],     sacc[2 * kb][1]);
                pf[1] = h2pack(sacc[2 * kb][2],     sacc[2 * kb][3]);
                pf[2] = h2pack(sacc[2 * kb + 1][0], sacc[2 * kb + 1][1]);
                pf[3] = h2pack(sacc[2 * kb + 1][2], sacc[2 * kb + 1][3]);
#pragma unroll
                for (int nb = 0; nb < 8; nb++) {
                    uint2 bv = *(uint2*)&sVf[kb * 512 + nb * 64 +
                                             (physC ^ ((nb & 1) << 3)) * 2];
                    mma_f16(oacc[nb], pf, &bv.x);
                }
            }
        }
        __syncthreads();
    }

    float il0 = 1.f / l0, il1 = 1.f / l1;
    int r0 = q0 + warp * 16 + g;
#pragma unroll
    for (int ni = 0; ni < 8; ni++) {
        int d = ni * 8 + 2 * c;
        *(uint32_t*)(Ob + (long)r0 * Dc + d) =
            h2pack(oacc[ni][0] * il0, oacc[ni][1] * il0);
        *(uint32_t*)(Ob + (long)(r0 + 8) * Dc + d) =
            h2pack(oacc[ni][2] * il1, oacc[ni][3] * il1);
    }
}

// =====================================================================
// gemm_h v3: cp.async + ldmatrix multistage NT GEMM, BK=32.
// 128x128 block, 8 warps of 64x32 tiles, 3 stages, 2 CTA/SM.
// smem/stage 16KB: A 8KB (128 rows x 64B) + B 8KB.
// 64B-row swizzle: seg' = s ^ ((r>>1)&3)  (bank = 16*(r&1)+4*seg', 8 distinct).
// C = A[M,K] @ B[N,K]^T [+bias][gelu][+resid]; out fp16 or fp32.
// Requires M,N multiples of 128, K multiple of 32.
// =====================================================================
#define BM 128
#define BN 128
#define NST 3

__device__ __forceinline__ uint32_t swz64(int r, int s) {
    return (uint32_t)(r * 64 + ((s ^ ((r >> 1) & 3)) << 4));
}

__global__ __launch_bounds__(256, 2)
void gemm_h(const __half* __restrict__ A, int lda,
            const __half* __restrict__ B, int ldb,
            void* __restrict__ Cp, int ldc, int K,
            const float* __restrict__ bias,
            const float* __restrict__ resid, int doGelu, int outHalf)
{
    __shared__ __align__(16) char smem[NST * 16384];
    uint32_t sb = smem_u32(smem);

    int m0 = blockIdx.y * BM, n0 = blockIdx.x * BN;
    int tid = threadIdx.x, lane = tid & 31, warp = tid >> 5;
    int wm = (warp & 1) * 64, wn = (warp >> 1) * 32;
    int nb0 = wn >> 3;

    float acc[4][4][4];
#pragma unroll
    for (int i = 0; i < 4; i++)
#pragma unroll
        for (int jx = 0; jx < 4; jx++)
#pragma unroll
            for (int e = 0; e < 4; e++) acc[i][jx][e] = 0.f;

    // ---- staging roles: 2 segments per thread per tile (A and B) ----
    int r0s = tid >> 2, s0s = tid & 3;            // seg idx tid
    int r1s = (tid + 256) >> 2, s1s = tid & 3;    // seg idx tid+256 (s same: (tid+256)&3 == tid&3)
    const __half* Ap0 = A + (long)(m0 + r0s) * lda + s0s * 8;
    const __half* Ap1 = A + (long)(m0 + r1s) * lda + s1s * 8;
    const __half* Bp0 = B + (long)(n0 + r0s) * ldb + s0s * 8;
    const __half* Bp1 = B + (long)(n0 + r1s) * ldb + s1s * 8;
    uint32_t oA0 = swz64(r0s, s0s), oA1 = swz64(r1s, s1s);
    uint32_t oB0 = 8192 + oA0,      oB1 = 8192 + oA1;

    // ---- consumer ldmatrix base offsets (per ksub add seg +2) ----
    int rAc = wm + (lane & 15);
    int rBc[2];
    rBc[0] = (nb0 + ((lane >> 4) & 1)) * 8 + (lane & 7);
    rBc[1] = (nb0 + 2 + ((lane >> 4) & 1)) * 8 + (lane & 7);
    int sAc = lane >> 4;            // 0/1 within ksub
    int sBc = (lane >> 3) & 1;

    int nIter = K / 32;

    // ---- prologue: stages 0, 1 ----
    cpa16(sb + oA0, Ap0); cpa16(sb + oA1, Ap1);
    cpa16(sb + oB0, Bp0); cpa16(sb + oB1, Bp1);
    CP_COMMIT();
    if (nIter > 1) {
        cpa16(sb + 16384 + oA0, Ap0 + 32); cpa16(sb + 16384 + oA1, Ap1 + 32);
        cpa16(sb + 16384 + oB0, Bp0 + 32); cpa16(sb + 16384 + oB1, Bp1 + 32);
    }
    CP_COMMIT();

    int stg = 0;
    for (int it = 0; it < nIter; it++) {
        if (it + 1 < nIter) { CP_WAIT(1); } else { CP_WAIT(0); }
        __syncthreads();
        if (it + 2 < nIter) {
            int s2 = (it + 2) % NST;
            long ko = (long)(it + 2) * 32;
            uint32_t sbb = sb + s2 * 16384;
            cpa16(sbb + oA0, Ap0 + ko); cpa16(sbb + oA1, Ap1 + ko);
            cpa16(sbb + oB0, Bp0 + ko); cpa16(sbb + oB1, Bp1 + ko);
        }
        CP_COMMIT();

        uint32_t base = sb + stg * 16384;
#pragma unroll
        for (int ks = 0; ks < 2; ks++) {
            uint32_t af[4][4], bf[2][4];
#pragma unroll
            for (int mi = 0; mi < 4; mi++)
                ldsm4(af[mi], base + swz64(rAc + mi * 16, ks * 2 + sAc));
#pragma unroll
            for (int p = 0; p < 2; p++)
                ldsm4(bf[p], base + 8192 + swz64(rBc[p], ks * 2 + sBc));
#pragma unroll
            for (int mi = 0; mi < 4; mi++) {
                mma_f16(acc[mi][0], af[mi], &bf[0][0]);
                mma_f16(acc[mi][1], af[mi], &bf[0][2]);
                mma_f16(acc[mi][2], af[mi], &bf[1][0]);
                mma_f16(acc[mi][3], af[mi], &bf[1][2]);
            }
        }
        stg = (stg + 1 == NST) ? 0 : stg + 1;
    }

    // ---- epilogue (identical to R12/R16) ----
    int ge = lane >> 2, c2 = (lane & 3) * 2;
#pragma unroll
    for (int mi = 0; mi < 4; mi++) {
#pragma unroll
        for (int ni = 0; ni < 4; ni++) {
            int gm = m0 + wm + mi * 16 + ge;
            int gn = n0 + wn + ni * 8 + c2;
            float v0 = acc[mi][ni][0], v1 = acc[mi][ni][1];
            float v2 = acc[mi][ni][2], v3 = acc[mi][ni][3];
            if (bias) {
                float b0 = bias[gn], b1 = bias[gn + 1];
                v0 += b0; v1 += b1; v2 += b0; v3 += b1;
            }
            if (doGelu) { v0 = gelu_f(v0); v1 = gelu_f(v1); v2 = gelu_f(v2); v3 = gelu_f(v3); }
            if (resid) {
                const float* r0p = resid + (long)gm * ldc + gn;
                const float* r1p = resid + (long)(gm + 8) * ldc + gn;
                v0 += r0p[0]; v1 += r0p[1]; v2 += r1p[0]; v3 += r1p[1];
            }
            if (outHalf) {
                __half* C = (__half*)Cp;
                *(uint32_t*)(C + (long)gm * ldc + gn)       = h2pack(v0, v1);
                *(uint32_t*)(C + (long)(gm + 8) * ldc + gn) = h2pack(v2, v3);
            } else {
                float* C = (float*)Cp;
                *(float2*)(C + (long)gm * ldc + gn)       = make_float2(v0, v1);
                *(float2*)(C + (long)(gm + 8) * ldc + gn) = make_float2(v2, v3);
            }
        }
    }
}

// ---------------- dedicated logits kernel (M=2, fp32, memory-bound) ----------
__global__ __launch_bounds__(256)
void logits_k(const float* __restrict__ fin,
              const float* __restrict__ Wemb,
              float* __restrict__ out)
{
    __shared__ float f0[Dc], f1[Dc];
    int tid = threadIdx.x;
    for (int i = tid; i < Dc; i += 256) { f0[i] = fin[i]; f1[i] = fin[Dc + i]; }
    __syncthreads();
    int warp = tid >> 5, lane = tid & 31;
    long v = (long)blockIdx.x * 8 + warp;
    if (v >= Vc) return;
    const float* w = Wemb + v * Dc;
    float d0 = 0.f, d1 = 0.f;
    for (int i = lane * 4; i < Dc; i += 128) {
        float4 wv = *(const float4*)(w + i);
        d0 += wv.x * f0[i] + wv.y * f0[i+1] + wv.z * f0[i+2] + wv.w * f0[i+3];
        d1 += wv.x * f1[i] + wv.y * f1[i+1] + wv.z * f1[i+2] + wv.w * f1[i+3];
    }
#pragma unroll
    for (int o = 16; o > 0; o >>= 1) {
        d0 += __shfl_xor_sync(0xffffffff, d0, o);
        d1 += __shfl_xor_sync(0xffffffff, d1, o);
    }
    if (lane == 0) { out[v] = d0; out[(long)Vc + v] = d1; }
}

// ---------------- host-side launch helpers ----------------
static inline void launch_h(const __half* A, int lda, const __half* B, int ldb,
                            void* C, int ldc, int M, int N, int K,
                            const float* bias, const float* resid,
                            int gelu, int outHalf)
{
    dim3 g(N / BN, M / BM, 1);
    gemm_h<<<g, 256>>>(A, lda, B, ldb, C, ldc, K, bias, resid, gelu, outHalf);
}
static inline void launch_cvt(const float* s, __half* d, long n)
{
    long blocks = (n / 4 + 255) / 256;
    cvtk<<<(unsigned)blocks, 256>>>(s, d, n);
}
static inline void launch_cvt_s(const float* s, __half* d, long n,
                                long per, long strideDst, long off)
{
    long blocks = (n / 4 + 255) / 256;
    cvtk_s<<<(unsigned)blocks, 256>>>(s, d, n, per, strideDst, off);
}

extern "C" void kernel_launch(void* const* d_in, const int* in_sizes, int n_in,
                              void* d_out, int out_size)
{
    const int*   x    = (const int*)  d_in[0];
    const float* Wemb = (const float*)d_in[1];
    const float* pos  = (const float*)d_in[2];
    const float* Wq   = (const float*)d_in[3];
    const float* Wk   = (const float*)d_in[4];
    const float* Wv   = (const float*)d_in[5];
    const float* Wo   = (const float*)d_in[6];
    const float* bo   = (const float*)d_in[7];
    const float* n1s  = (const float*)d_in[8];
    const float* n1b  = (const float*)d_in[9];
    const float* n2s  = (const float*)d_in[10];
    const float* n2b  = (const float*)d_in[11];
    const float* W1   = (const float*)d_in[12];
    const float* b1   = (const float*)d_in[13];
    const float* W2   = (const float*)d_in[14];
    const float* b2   = (const float*)d_in[15];
    const float* fs   = (const float*)d_in[16];
    const float* fb   = (const float*)d_in[17];
    float* out = (float*)d_out;

    float  *h, *fin;
    __half *xnh, *qkvh, *ctxh, *ffh;
    __half *wqkv16, *wo16, *w116, *w216;
    cudaGetSymbolAddress((void**)&h,     g_h);
    cudaGetSymbolAddress((void**)&fin,   g_fin);
    cudaGetSymbolAddress((void**)&xnh,   g_xnh);
    cudaGetSymbolAddress((void**)&qkvh,  g_qkvh);
    cudaGetSymbolAddress((void**)&ctxh,  g_ctxh);
    cudaGetSymbolAddress((void**)&ffh,   g_ffh);
    cudaGetSymbolAddress((void**)&wqkv16,g_wqkv16);
    cudaGetSymbolAddress((void**)&wo16,  g_wo16);
    cudaGetSymbolAddress((void**)&w116,  g_w116);
    cudaGetSymbolAddress((void**)&w216,  g_w216);

    const long TD = (long)Tc * Dc;
    const long DD = (long)Dc * Dc;
    const long FD = (long)DFFc * Dc;
    const int  D3 = 3 * Dc;

    // weights -> fp16 (once per launch; graph-capturable)
    launch_cvt_s(Wq, wqkv16, (long)Lc * DD, DD, 3 * DD, 0);
    launch_cvt_s(Wk, wqkv16, (long)Lc * DD, DD, 3 * DD, DD);
    launch_cvt_s(Wv, wqkv16, (long)Lc * DD, DD, 3 * DD, 2 * DD);
    launch_cvt(Wo, wo16, (long)Lc * DD);
    launch_cvt(W1, w116, (long)Lc * FD);
    launch_cvt(W2, w216, (long)Lc * FD);

    {
        long n = (long)BTc * Dc;
        embed_k<<<(unsigned)((n + 255) / 256), 256>>>(x, Wemb, pos, h);
    }

    for (int l = 0; l < Lc; l++) {
        const float* bol = bo + (long)l * Dc;
        const float* b1l = b1 + (long)l * DFFc;
        const float* b2l = b2 + (long)l * Dc;

        // LN1 -> fp16
        ln_k<<<BTc, 256>>>(h, Dc, xnh, Dc, 1, n1s + (long)l * Dc, n1b + (long)l * Dc);

        // QKV = xn @ Wqkv^T  (fused, fp16 in/out, N=3072)
        launch_h(xnh, Dc, wqkv16 + (long)l * 3 * DD, Dc, qkvh, D3,
                 BTc, D3, Dc, 0, 0, 0, 1);

        // fused causal attention (fp16 I/O, QKV row stride 3*Dc)
        {
            dim3 fg(Tc / 128, Bc * Hc);
            flash_k<<<fg, 256>>>(qkvh, qkvh + Dc, qkvh + 2 * Dc, ctxh, D3);
        }

        // h = h + ctx @ Wo^T + bo  (fp32 out)
        launch_h(ctxh, Dc, wo16 + (long)l * DD, Dc, h, Dc, BTc, Dc, Dc, bol, h, 0, 0);

        // LN2 -> fp16
        ln_k<<<BTc, 256>>>(h, Dc, xnh, Dc, 1, n2s + (long)l * Dc, n2b + (long)l * Dc);

        // ff = gelu(xn @ W1^T + b1)  (fp16 out)
        launch_h(xnh, Dc, w116 + (long)l * FD, Dc, ffh, DFFc, BTc, DFFc, Dc, b1l, 0, 1, 1);

        // h = h + ff @ W2^T + b2  (fp32 out)
        launch_h(ffh, DFFc, w216 + (long)l * FD, DFFc, h, Dc, BTc, Dc, DFFc, b2l, h, 0, 0);
    }

    // final LN on the 2 last-token rows only -> fp32
    ln_k<<<Bc, 256>>>(h + (long)(Tc - 1) * Dc, TD, fin, Dc, 0, fs, fb);

    // logits (fp32, memory-bound dedicated kernel)
    logits_k<<<(Vc + 7) / 8, 256>>>(fin, Wemb, out);
}